// round 11
// baseline (speedup 1.0000x reference)
#include <cuda_runtime.h>
#include <math.h>
#include <stdint.h>

// ---------------------------------------------------------------------------
// Problem constants: B=32, H=W=64, C=256, NH=8, hd=32, WS=8, SS=4, IM=4
// ---------------------------------------------------------------------------
#define M_TOK   131072
#define C_DIM   256
#define DFF     1024

// Scratch (device globals; no allocation at runtime)
__device__ float g_xw   [M_TOK * C_DIM];
__device__ float g_qkv  [M_TOK * 768];
__device__ float g_att  [M_TOK * C_DIM];
__device__ float g_hs   [M_TOK * C_DIM];
__device__ float g_y    [M_TOK * C_DIM];
__device__ float g_mid  [M_TOK * DFF];
__device__ float g_wqkv [C_DIM * 768];
__device__ float g_bqkv [768];

// ---------------------------------------------------------------------------
// cp.async helpers
// ---------------------------------------------------------------------------
__device__ __forceinline__ void cp_async16(void* smem, const void* gmem) {
    uint32_t s = (uint32_t)__cvta_generic_to_shared(smem);
    asm volatile("cp.async.cg.shared.global [%0], [%1], 16;\n" :: "r"(s), "l"(gmem));
}
__device__ __forceinline__ void cp_commit() {
    asm volatile("cp.async.commit_group;\n");
}
template<int N>
__device__ __forceinline__ void cp_wait() {
    asm volatile("cp.async.wait_group %0;\n" :: "n"(N));
}

__device__ __forceinline__ void mma_tf32(float d[4], const uint32_t a[4], const uint32_t b[2]) {
    asm volatile(
        "mma.sync.aligned.m16n8k8.row.col.f32.tf32.tf32.f32 "
        "{%0,%1,%2,%3}, {%4,%5,%6,%7}, {%8,%9}, {%0,%1,%2,%3};\n"
        : "+f"(d[0]), "+f"(d[1]), "+f"(d[2]), "+f"(d[3])
        : "r"(a[0]), "r"(a[1]), "r"(a[2]), "r"(a[3]), "r"(b[0]), "r"(b[1]));
}

// ---------------------------------------------------------------------------
// Pack wq|wk|wv -> [256,768], bq|bk|bv -> [768]
// ---------------------------------------------------------------------------
__global__ __launch_bounds__(256) void pack_qkv(
    const float* __restrict__ wq, const float* __restrict__ wk,
    const float* __restrict__ wv, const float* __restrict__ bq,
    const float* __restrict__ bk, const float* __restrict__ bv,
    float* __restrict__ wdst, float* __restrict__ bdst)
{
    int idx = blockIdx.x * 256 + threadIdx.x;
    int k = idx / 768, n = idx % 768;
    float v = (n < 256) ? wq[k * 256 + n]
            : (n < 512) ? wk[k * 256 + n - 256]
                        : wv[k * 256 + n - 512];
    wdst[idx] = v;
    if (idx < 768)
        bdst[idx] = (idx < 256) ? bq[idx] : (idx < 512) ? bk[idx - 256] : bv[idx - 512];
}

// ---------------------------------------------------------------------------
// LayerNorm: warp-per-token, 8 tokens/block, float4 I/O. (LN1 only)
// ---------------------------------------------------------------------------
__global__ __launch_bounds__(256) void ln_kernel(
    const float* __restrict__ x, const float* __restrict__ g,
    const float* __restrict__ bb, float* __restrict__ out, int gather)
{
    int warp = threadIdx.x >> 5, lane = threadIdx.x & 31;
    int r = blockIdx.x * 8 + warp;
    long src;
    if (gather) {
        int b  = r >> 12;
        int wi = (r >> 9) & 7, wj = (r >> 6) & 7;
        int pi = (r >> 3) & 7, pj = r & 7;
        int h = (wi * 8 + pi + 4) & 63;
        int w = (wj * 8 + pj + 4) & 63;
        src = (long)b * 4096 + h * 64 + w;
    } else {
        src = r;
    }
    const float4* xp = (const float4*)(x + src * C_DIM);
    float4 v0 = xp[lane * 2], v1 = xp[lane * 2 + 1];
    float s  = v0.x + v0.y + v0.z + v0.w + v1.x + v1.y + v1.z + v1.w;
    float s2 = v0.x*v0.x + v0.y*v0.y + v0.z*v0.z + v0.w*v0.w
             + v1.x*v1.x + v1.y*v1.y + v1.z*v1.z + v1.w*v1.w;
    #pragma unroll
    for (int o = 16; o > 0; o >>= 1) {
        s  += __shfl_xor_sync(0xffffffffu, s, o);
        s2 += __shfl_xor_sync(0xffffffffu, s2, o);
    }
    float mean = s * (1.f / 256.f);
    float var  = s2 * (1.f / 256.f) - mean * mean;
    float rstd = rsqrtf(var + 1e-5f);
    const float4* gp = (const float4*)(g  + lane * 8);
    const float4* bp = (const float4*)(bb + lane * 8);
    float4 g0 = gp[0], g1 = gp[1], b0 = bp[0], b1 = bp[1];
    float4 o0, o1;
    o0.x = (v0.x - mean) * rstd * g0.x + b0.x;
    o0.y = (v0.y - mean) * rstd * g0.y + b0.y;
    o0.z = (v0.z - mean) * rstd * g0.z + b0.z;
    o0.w = (v0.w - mean) * rstd * g0.w + b0.w;
    o1.x = (v1.x - mean) * rstd * g1.x + b1.x;
    o1.y = (v1.y - mean) * rstd * g1.y + b1.y;
    o1.z = (v1.z - mean) * rstd * g1.z + b1.z;
    o1.w = (v1.w - mean) * rstd * g1.w + b1.w;
    float4* op = (float4*)(out + (long)r * C_DIM + lane * 8);
    op[0] = o0; op[1] = o1;
}

// ---------------------------------------------------------------------------
// TF32 tensor-core GEMM: C = epi(A[MxK] @ B[KxN] + bias)
// EPI 0: plain. 1: GELU. 2: scatter+residual -> hs AND fused LN2 -> Y.
// EPI 3: residual.   EPI==2 requires BN == N.
// R11: software-pipelined mainloop — next-stage cp.async issued right after
// the barrier, ALL fragments (both ks) loaded before any MMA.
// ---------------------------------------------------------------------------
#define NSTG 3
#define BM   128
#define BN   256
#define ASTR 20
#define BSTR 264
#define A_STAGE (BM * ASTR)
#define B_STAGE (16 * BSTR)
#define SMEM_SZ ((NSTG * (A_STAGE + B_STAGE)) * 4)

template<int EPI>
__global__ __launch_bounds__(256, 1) void tf32gemm(
    const float* __restrict__ A, const float* __restrict__ B,
    const float* __restrict__ bias, const float* __restrict__ R,
    float* __restrict__ C, int M, int N, int K,
    const float* __restrict__ G2, const float* __restrict__ B2,
    float* __restrict__ Y)
{
    extern __shared__ float sm[];
    float* Asm = sm;
    float* Bsm = sm + NSTG * A_STAGE;

    int tid  = threadIdx.x;
    int lane = tid & 31, warp = tid >> 5;
    int wm = warp >> 2, wn = warp & 3;
    int bm = blockIdx.y * BM, bn = blockIdx.x * BN;
    int gid = lane >> 2, tig = lane & 3;

    float acc[4][8][4];
    #pragma unroll
    for (int mt = 0; mt < 4; mt++)
        #pragma unroll
        for (int nt = 0; nt < 8; nt++)
            #pragma unroll
            for (int i = 0; i < 4; i++) acc[mt][nt][i] = 0.f;

    int aR[2], aC[2], bR[4], bC[4];
    #pragma unroll
    for (int i = 0; i < 2; i++) {
        int s = tid + i * 256;
        aR[i] = s >> 2;  aC[i] = (s & 3) * 4;
    }
    #pragma unroll
    for (int i = 0; i < 4; i++) {
        int s = tid + i * 256;
        bR[i] = s >> 6;  bC[i] = (s & 63) * 4;
    }

    int KT = K >> 4;

    #pragma unroll
    for (int s = 0; s < NSTG - 1; s++) {
        int kb = s << 4;
        float* as = Asm + s * A_STAGE;
        float* bs = Bsm + s * B_STAGE;
        #pragma unroll
        for (int i = 0; i < 2; i++)
            cp_async16(&as[aR[i] * ASTR + aC[i]], A + (long)(bm + aR[i]) * K + kb + aC[i]);
        #pragma unroll
        for (int i = 0; i < 4; i++)
            cp_async16(&bs[bR[i] * BSTR + bC[i]], B + (long)(kb + bR[i]) * N + bn + bC[i]);
        cp_commit();
    }

    for (int kt = 0; kt < KT; kt++) {
        if (kt + NSTG - 1 < KT) cp_wait<NSTG - 2>(); else cp_wait<0>();
        __syncthreads();
        int stg = kt % NSTG;
        const float* as = Asm + stg * A_STAGE;
        const float* bs = Bsm + stg * B_STAGE;

        // 1) kick off next-stage DMA immediately (overlaps with MMA work).
        //    Target buffer (kt-1)%NSTG was consumed last iteration; the
        //    barrier above guarantees all warps are done with it.
        if (kt + NSTG - 1 < KT) {
            int kn = kt + NSTG - 1;
            int kb = kn << 4;
            int ds = kn % NSTG;
            float* asn = Asm + ds * A_STAGE;
            float* bsn = Bsm + ds * B_STAGE;
            #pragma unroll
            for (int i = 0; i < 2; i++)
                cp_async16(&asn[aR[i] * ASTR + aC[i]], A + (long)(bm + aR[i]) * K + kb + aC[i]);
            #pragma unroll
            for (int i = 0; i < 4; i++)
                cp_async16(&bsn[bR[i] * BSTR + bC[i]], B + (long)(kb + bR[i]) * N + bn + bC[i]);
            cp_commit();
        }

        // 2) load ALL fragments (both ks sub-steps) before any MMA, so the
        //    ks=1 LDS latency hides under the ks=0 MMA train.
        uint32_t af[2][4][4], bf[2][8][2];
        #pragma unroll
        for (int ks = 0; ks < 2; ks++) {
            #pragma unroll
            for (int mt = 0; mt < 4; mt++) {
                int r0 = wm * 64 + mt * 16 + gid;
                int c0 = ks * 8 + tig;
                af[ks][mt][0] = __float_as_uint(as[r0 * ASTR + c0]);
                af[ks][mt][1] = __float_as_uint(as[(r0 + 8) * ASTR + c0]);
                af[ks][mt][2] = __float_as_uint(as[r0 * ASTR + c0 + 4]);
                af[ks][mt][3] = __float_as_uint(as[(r0 + 8) * ASTR + c0 + 4]);
            }
            #pragma unroll
            for (int nt = 0; nt < 8; nt++) {
                int rr = ks * 8 + tig;
                int cc = wn * 64 + nt * 8 + gid;
                bf[ks][nt][0] = __float_as_uint(bs[rr * BSTR + cc]);
                bf[ks][nt][1] = __float_as_uint(bs[(rr + 4) * BSTR + cc]);
            }
        }
        // 3) MMA trains
        #pragma unroll
        for (int ks = 0; ks < 2; ks++)
            #pragma unroll
            for (int mt = 0; mt < 4; mt++)
                #pragma unroll
                for (int nt = 0; nt < 8; nt++)
                    mma_tf32(acc[mt][nt], af[ks][mt], bf[ks][nt]);
    }

    if (EPI == 2) {
        // ---- fused: hs = GEMM + bias + residual (scattered), y = LN(hs) ----
        __syncthreads();                 // before reusing smem for reduction
        float* red = sm;                 // 128 rows x (4 warps x {sum,sq}) = 4KB
        long orows[4][2];
        float rsum[4][2], rsq[4][2];
        #pragma unroll
        for (int mt = 0; mt < 4; mt++) {
            #pragma unroll
            for (int half = 0; half < 2; half++) {
                int row = bm + wm * 64 + mt * 16 + half * 8 + gid;
                int b  = row >> 12;
                int wi = (row >> 9) & 7, wj = (row >> 6) & 7;
                int pi = (row >> 3) & 7, pj = row & 7;
                int h = (wi * 8 + pi + 4) & 63;
                int w = (wj * 8 + pj + 4) & 63;
                long orow = (long)b * 4096 + h * 64 + w;
                orows[mt][half] = orow;
                float s = 0.f, q = 0.f;
                #pragma unroll
                for (int nt = 0; nt < 8; nt++) {
                    int col = bn + wn * 64 + nt * 8 + 2 * tig;
                    float v0 = acc[mt][nt][half * 2 + 0] + bias[col];
                    float v1 = acc[mt][nt][half * 2 + 1] + bias[col + 1];
                    float2 rr = *(const float2*)(R + orow * N + col);
                    v0 += rr.x; v1 += rr.y;
                    acc[mt][nt][half * 2 + 0] = v0;
                    acc[mt][nt][half * 2 + 1] = v1;
                    s += v0 + v1;
                    q += v0 * v0 + v1 * v1;
                    float2 o; o.x = v0; o.y = v1;
                    *(float2*)(C + orow * N + col) = o;
                }
                rsum[mt][half] = s; rsq[mt][half] = q;
            }
        }
        #pragma unroll
        for (int mt = 0; mt < 4; mt++) {
            #pragma unroll
            for (int half = 0; half < 2; half++) {
                float s = rsum[mt][half], q = rsq[mt][half];
                s += __shfl_xor_sync(0xffffffffu, s, 1);
                q += __shfl_xor_sync(0xffffffffu, q, 1);
                s += __shfl_xor_sync(0xffffffffu, s, 2);
                q += __shfl_xor_sync(0xffffffffu, q, 2);
                if (tig == 0) {
                    int lr = wm * 64 + mt * 16 + half * 8 + gid;
                    red[lr * 8 + wn * 2]     = s;
                    red[lr * 8 + wn * 2 + 1] = q;
                }
            }
        }
        __syncthreads();
        #pragma unroll
        for (int mt = 0; mt < 4; mt++) {
            #pragma unroll
            for (int half = 0; half < 2; half++) {
                int lr = wm * 64 + mt * 16 + half * 8 + gid;
                float s = red[lr*8+0] + red[lr*8+2] + red[lr*8+4] + red[lr*8+6];
                float q = red[lr*8+1] + red[lr*8+3] + red[lr*8+5] + red[lr*8+7];
                float mean = s * (1.f / 256.f);
                float var  = q * (1.f / 256.f) - mean * mean;
                float rstd = rsqrtf(var + 1e-5f);
                long orow = orows[mt][half];
                #pragma unroll
                for (int nt = 0; nt < 8; nt++) {
                    int col = bn + wn * 64 + nt * 8 + 2 * tig;
                    float v0 = acc[mt][nt][half * 2 + 0];
                    float v1 = acc[mt][nt][half * 2 + 1];
                    float2 o;
                    o.x = (v0 - mean) * rstd * G2[col]     + B2[col];
                    o.y = (v1 - mean) * rstd * G2[col + 1] + B2[col + 1];
                    *(float2*)(Y + orow * N + col) = o;
                }
            }
        }
        return;
    }

    // ---- standard epilogues (EPI 0, 1, 3) ----
    #pragma unroll
    for (int mt = 0; mt < 4; mt++) {
        #pragma unroll
        for (int half = 0; half < 2; half++) {
            int row = bm + wm * 64 + mt * 16 + half * 8 + gid;
            long orow = row;
            #pragma unroll
            for (int nt = 0; nt < 8; nt++) {
                int col = bn + wn * 64 + nt * 8 + 2 * tig;
                float v0 = acc[mt][nt][half * 2 + 0] + bias[col];
                float v1 = acc[mt][nt][half * 2 + 1] + bias[col + 1];
                if (EPI == 1) {
                    v0 = 0.5f * v0 * (1.f + erff(v0 * 0.70710678118654752f));
                    v1 = 0.5f * v1 * (1.f + erff(v1 * 0.70710678118654752f));
                }
                if (EPI == 3) {
                    float2 rr = *(const float2*)(R + orow * N + col);
                    v0 += rr.x; v1 += rr.y;
                }
                float2 o; o.x = v0; o.y = v1;
                *(float2*)(C + orow * N + col) = o;
            }
        }
    }
}

// ---------------------------------------------------------------------------
// Tensor-core windowed attention, 1xTF32 (direct fp32-bit fragments).
// One block = one (window, head), 128 threads / 4 warps.
// Conflict-free strides: Q/K 36, V 40, P 68.
// ---------------------------------------------------------------------------
#define QSTR 36
#define VSTR 40
#define PSTR 68

__device__ __forceinline__ int bandf(int z) { return z < 56 ? 0 : (z < 60 ? 1 : 2); }

__global__ __launch_bounds__(128) void attn_kernel(
    const float* __restrict__ QKV, const float* __restrict__ bt,
    float* __restrict__ O)
{
    __shared__ float Qs[64 * QSTR];
    __shared__ float Ks[64 * QSTR];
    __shared__ float Vs[64 * VSTR];
    __shared__ float Ps[64 * PSTR];
    __shared__ float btS[228];

    int win  = blockIdx.x;
    int head = blockIdx.y;
    int t = threadIdx.x;
    int warp = t >> 5, lane = t & 31;
    int gid = lane >> 2, tig = lane & 3;
    long base = (long)win * 64 * 768 + head * 32;

    for (int i = t; i < 225; i += 128) btS[i] = bt[i * 8 + head];

    const float scale = 0.17677669529663687f;   // 32^-0.5
    #pragma unroll
    for (int i = 0; i < 4; i++) {
        int idx = t + i * 128;
        int row = idx >> 3, c4 = (idx & 7) * 4;
        const float* src = QKV + base + (long)row * 768 + c4;
        float4 q = *(const float4*)(src);
        q.x *= scale; q.y *= scale; q.z *= scale; q.w *= scale;
        *(float4*)&Qs[row * QSTR + c4] = q;
        *(float4*)&Ks[row * QSTR + c4] = *(const float4*)(src + 256);
        *(float4*)&Vs[row * VSTR + c4] = *(const float4*)(src + 512);
    }
    __syncthreads();

    // ---- S = Q@K^T : warp covers key-cols [warp*16, warp*16+16) ----
    float sc[4][2][4];
    #pragma unroll
    for (int mt = 0; mt < 4; mt++)
        #pragma unroll
        for (int nt = 0; nt < 2; nt++)
            #pragma unroll
            for (int i = 0; i < 4; i++) sc[mt][nt][i] = 0.f;

    #pragma unroll
    for (int kt = 0; kt < 4; kt++) {
        uint32_t af[4][4], bf[2][2];
        #pragma unroll
        for (int mt = 0; mt < 4; mt++) {
            int r0 = mt * 16 + gid;
            int c0 = kt * 8 + tig;
            af[mt][0] = __float_as_uint(Qs[r0 * QSTR + c0]);
            af[mt][1] = __float_as_uint(Qs[(r0 + 8) * QSTR + c0]);
            af[mt][2] = __float_as_uint(Qs[r0 * QSTR + c0 + 4]);
            af[mt][3] = __float_as_uint(Qs[(r0 + 8) * QSTR + c0 + 4]);
        }
        #pragma unroll
        for (int nt = 0; nt < 2; nt++) {
            int kr = warp * 16 + nt * 8 + gid;
            int kc = kt * 8 + tig;
            bf[nt][0] = __float_as_uint(Ks[kr * QSTR + kc]);
            bf[nt][1] = __float_as_uint(Ks[kr * QSTR + kc + 4]);
        }
        #pragma unroll
        for (int mt = 0; mt < 4; mt++)
            #pragma unroll
            for (int nt = 0; nt < 2; nt++)
                mma_tf32(sc[mt][nt], af[mt], bf[nt]);
    }

    // ---- bias + shift mask, store S to Ps ----
    int w_in_b = win & 63;
    int wwi = w_in_b >> 3, wwj = w_in_b & 7;
    bool edge = (wwi == 7) || (wwj == 7);
    #pragma unroll
    for (int mt = 0; mt < 4; mt++) {
        #pragma unroll
        for (int half = 0; half < 2; half++) {
            int r = mt * 16 + half * 8 + gid;
            int yi = r >> 3, xi = r & 7;
            int id_i = edge ? bandf(wwi * 8 + yi) * 3 + bandf(wwj * 8 + xi) : 0;
            #pragma unroll
            for (int nt = 0; nt < 2; nt++) {
                int c0 = warp * 16 + nt * 8 + 2 * tig;
                float v0 = sc[mt][nt][half * 2 + 0];
                float v1 = sc[mt][nt][half * 2 + 1];
                #pragma unroll
                for (int j = 0; j < 2; j++) {
                    int c = c0 + j;
                    int yj = c >> 3, xj = c & 7;
                    float add = btS[(yi - yj + 7) * 15 + (xi - xj + 7)];
                    if (edge) {
                        int id_j = bandf(wwi * 8 + yj) * 3 + bandf(wwj * 8 + xj);
                        if (id_i != id_j) add -= 100.f;
                    }
                    if (j == 0) v0 += add; else v1 += add;
                }
                float2 st; st.x = v0; st.y = v1;
                *(float2*)&Ps[r * PSTR + c0] = st;
            }
        }
    }
    __syncthreads();

    // ---- softmax: thread handles half a row ----
    {
        int row = t >> 1;
        int c0 = (t & 1) * 32;
        float4 e[8];
        float mx = -1e30f;
        #pragma unroll
        for (int i = 0; i < 8; i++) {
            e[i] = *(const float4*)&Ps[row * PSTR + c0 + i * 4];
            mx = fmaxf(mx, fmaxf(fmaxf(e[i].x, e[i].y), fmaxf(e[i].z, e[i].w)));
        }
        mx = fmaxf(mx, __shfl_xor_sync(0xffffffffu, mx, 1));
        float sum = 0.f;
        #pragma unroll
        for (int i = 0; i < 8; i++) {
            e[i].x = __expf(e[i].x - mx); e[i].y = __expf(e[i].y - mx);
            e[i].z = __expf(e[i].z - mx); e[i].w = __expf(e[i].w - mx);
            sum += e[i].x + e[i].y + e[i].z + e[i].w;
        }
        sum += __shfl_xor_sync(0xffffffffu, sum, 1);
        float rs = 1.f / sum;
        #pragma unroll
        for (int i = 0; i < 8; i++) {
            e[i].x *= rs; e[i].y *= rs; e[i].z *= rs; e[i].w *= rs;
            *(float4*)&Ps[row * PSTR + c0 + i * 4] = e[i];
        }
    }
    __syncthreads();

    // ---- O = P@V : warp covers query-rows [warp*16, warp*16+16) ----
    float oc[4][4];
    #pragma unroll
    for (int nt = 0; nt < 4; nt++)
        #pragma unroll
        for (int i = 0; i < 4; i++) oc[nt][i] = 0.f;

    #pragma unroll
    for (int kt = 0; kt < 8; kt++) {
        uint32_t af[4], bf[4][2];
        int r0 = warp * 16 + gid;
        int c0 = kt * 8 + tig;
        af[0] = __float_as_uint(Ps[r0 * PSTR + c0]);
        af[1] = __float_as_uint(Ps[(r0 + 8) * PSTR + c0]);
        af[2] = __float_as_uint(Ps[r0 * PSTR + c0 + 4]);
        af[3] = __float_as_uint(Ps[(r0 + 8) * PSTR + c0 + 4]);
        #pragma unroll
        for (int nt = 0; nt < 4; nt++) {
            int vr = kt * 8 + tig;
            int vc = nt * 8 + gid;
            bf[nt][0] = __float_as_uint(Vs[vr * VSTR + vc]);
            bf[nt][1] = __float_as_uint(Vs[(vr + 4) * VSTR + vc]);
        }
        #pragma unroll
        for (int nt = 0; nt < 4; nt++)
            mma_tf32(oc[nt], af, bf[nt]);
    }

    // ---- write O ----
    long obase = ((long)win * 64) * C_DIM + head * 32;
    #pragma unroll
    for (int half = 0; half < 2; half++) {
        int row = warp * 16 + half * 8 + gid;
        #pragma unroll
        for (int nt = 0; nt < 4; nt++) {
            int col = nt * 8 + 2 * tig;
            float2 o;
            o.x = oc[nt][half * 2 + 0];
            o.y = oc[nt][half * 2 + 1];
            *(float2*)(O + obase + (long)row * C_DIM + col) = o;
        }
    }
}

// ---------------------------------------------------------------------------
// Launch
// ---------------------------------------------------------------------------
extern "C" void kernel_launch(void* const* d_in, const int* in_sizes, int n_in,
                              void* d_out, int out_size)
{
    const float* hidden = (const float*)d_in[0];
    const float* ln1_g  = (const float*)d_in[1];
    const float* ln1_b  = (const float*)d_in[2];
    const float* wq     = (const float*)d_in[3];
    const float* bq     = (const float*)d_in[4];
    const float* wk     = (const float*)d_in[5];
    const float* bk     = (const float*)d_in[6];
    const float* wv     = (const float*)d_in[7];
    const float* bv     = (const float*)d_in[8];
    const float* bt     = (const float*)d_in[9];
    const float* wo     = (const float*)d_in[10];
    const float* bo     = (const float*)d_in[11];
    const float* ln2_g  = (const float*)d_in[12];
    const float* ln2_b  = (const float*)d_in[13];
    const float* w1     = (const float*)d_in[14];
    const float* b1     = (const float*)d_in[15];
    const float* w2     = (const float*)d_in[16];
    const float* b2     = (const float*)d_in[17];
    float* out = (float*)d_out;

    float *p_xw, *p_qkv, *p_att, *p_hs, *p_y, *p_mid, *p_wqkv, *p_bqkv;
    cudaGetSymbolAddress((void**)&p_xw,   g_xw);
    cudaGetSymbolAddress((void**)&p_qkv,  g_qkv);
    cudaGetSymbolAddress((void**)&p_att,  g_att);
    cudaGetSymbolAddress((void**)&p_hs,   g_hs);
    cudaGetSymbolAddress((void**)&p_y,    g_y);
    cudaGetSymbolAddress((void**)&p_mid,  g_mid);
    cudaGetSymbolAddress((void**)&p_wqkv, g_wqkv);
    cudaGetSymbolAddress((void**)&p_bqkv, g_bqkv);

    cudaFuncSetAttribute(tf32gemm<0>, cudaFuncAttributeMaxDynamicSharedMemorySize, SMEM_SZ);
    cudaFuncSetAttribute(tf32gemm<1>, cudaFuncAttributeMaxDynamicSharedMemorySize, SMEM_SZ);
    cudaFuncSetAttribute(tf32gemm<2>, cudaFuncAttributeMaxDynamicSharedMemorySize, SMEM_SZ);
    cudaFuncSetAttribute(tf32gemm<3>, cudaFuncAttributeMaxDynamicSharedMemorySize, SMEM_SZ);

    dim3 blk(256);

    pack_qkv<<<768, blk>>>(wq, wk, wv, bq, bk, bv, p_wqkv, p_bqkv);
    ln_kernel<<<M_TOK / 8, blk>>>(hidden, ln1_g, ln1_b, p_xw, 1);
    tf32gemm<0><<<dim3(768 / BN, M_TOK / BM), blk, SMEM_SZ>>>(
        p_xw, p_wqkv, p_bqkv, nullptr, p_qkv, M_TOK, 768, C_DIM,
        nullptr, nullptr, nullptr);
    attn_kernel<<<dim3(2048, 8), dim3(128)>>>(p_qkv, bt, p_att);
    // wo-projection + scatter + residual -> hs, fused LN2 -> y
    tf32gemm<2><<<dim3(C_DIM / BN, M_TOK / BM), blk, SMEM_SZ>>>(
        p_att, wo, bo, hidden, p_hs, M_TOK, C_DIM, C_DIM,
        ln2_g, ln2_b, p_y);
    tf32gemm<1><<<dim3(DFF / BN, M_TOK / BM), blk, SMEM_SZ>>>(
        p_y, w1, b1, nullptr, p_mid, M_TOK, DFF, C_DIM,
        nullptr, nullptr, nullptr);
    tf32gemm<3><<<dim3(C_DIM / BN, M_TOK / BM), blk, SMEM_SZ>>>(
        p_mid, w2, b2, p_hs, out, M_TOK, C_DIM, DFF,
        nullptr, nullptr, nullptr);
}

// round 12
// speedup vs baseline: 1.1286x; 1.1286x over previous
#include <cuda_runtime.h>
#include <math.h>
#include <stdint.h>

// ---------------------------------------------------------------------------
// Problem constants: B=32, H=W=64, C=256, NH=8, hd=32, WS=8, SS=4, IM=4
// ---------------------------------------------------------------------------
#define M_TOK   131072
#define C_DIM   256
#define DFF     1024

// Scratch (device globals; no allocation at runtime)
__device__ float g_xw   [M_TOK * C_DIM];
__device__ float g_qkv  [M_TOK * 768];
__device__ float g_att  [M_TOK * C_DIM];
__device__ float g_hs   [M_TOK * C_DIM];
__device__ float g_y    [M_TOK * C_DIM];
__device__ float g_mid  [M_TOK * DFF];
__device__ float g_wqkv [C_DIM * 768];
__device__ float g_bqkv [768];

// ---------------------------------------------------------------------------
// cp.async helpers
// ---------------------------------------------------------------------------
__device__ __forceinline__ void cp_async16(void* smem, const void* gmem) {
    uint32_t s = (uint32_t)__cvta_generic_to_shared(smem);
    asm volatile("cp.async.cg.shared.global [%0], [%1], 16;\n" :: "r"(s), "l"(gmem));
}
__device__ __forceinline__ void cp_commit() {
    asm volatile("cp.async.commit_group;\n");
}
template<int N>
__device__ __forceinline__ void cp_wait() {
    asm volatile("cp.async.wait_group %0;\n" :: "n"(N));
}

__device__ __forceinline__ void mma_tf32(float d[4], const uint32_t a[4], const uint32_t b[2]) {
    asm volatile(
        "mma.sync.aligned.m16n8k8.row.col.f32.tf32.tf32.f32 "
        "{%0,%1,%2,%3}, {%4,%5,%6,%7}, {%8,%9}, {%0,%1,%2,%3};\n"
        : "+f"(d[0]), "+f"(d[1]), "+f"(d[2]), "+f"(d[3])
        : "r"(a[0]), "r"(a[1]), "r"(a[2]), "r"(a[3]), "r"(b[0]), "r"(b[1]));
}

// ---------------------------------------------------------------------------
// Pack wq|wk|wv -> [256,768], bq|bk|bv -> [768]
// ---------------------------------------------------------------------------
__global__ __launch_bounds__(256) void pack_qkv(
    const float* __restrict__ wq, const float* __restrict__ wk,
    const float* __restrict__ wv, const float* __restrict__ bq,
    const float* __restrict__ bk, const float* __restrict__ bv,
    float* __restrict__ wdst, float* __restrict__ bdst)
{
    int idx = blockIdx.x * 256 + threadIdx.x;
    int k = idx / 768, n = idx % 768;
    float v = (n < 256) ? wq[k * 256 + n]
            : (n < 512) ? wk[k * 256 + n - 256]
                        : wv[k * 256 + n - 512];
    wdst[idx] = v;
    if (idx < 768)
        bdst[idx] = (idx < 256) ? bq[idx] : (idx < 512) ? bk[idx - 256] : bv[idx - 512];
}

// ---------------------------------------------------------------------------
// LayerNorm: warp-per-token, 8 tokens/block, float4 I/O. (LN1 only)
// ---------------------------------------------------------------------------
__global__ __launch_bounds__(256) void ln_kernel(
    const float* __restrict__ x, const float* __restrict__ g,
    const float* __restrict__ bb, float* __restrict__ out, int gather)
{
    int warp = threadIdx.x >> 5, lane = threadIdx.x & 31;
    int r = blockIdx.x * 8 + warp;
    long src;
    if (gather) {
        int b  = r >> 12;
        int wi = (r >> 9) & 7, wj = (r >> 6) & 7;
        int pi = (r >> 3) & 7, pj = r & 7;
        int h = (wi * 8 + pi + 4) & 63;
        int w = (wj * 8 + pj + 4) & 63;
        src = (long)b * 4096 + h * 64 + w;
    } else {
        src = r;
    }
    const float4* xp = (const float4*)(x + src * C_DIM);
    float4 v0 = xp[lane * 2], v1 = xp[lane * 2 + 1];
    float s  = v0.x + v0.y + v0.z + v0.w + v1.x + v1.y + v1.z + v1.w;
    float s2 = v0.x*v0.x + v0.y*v0.y + v0.z*v0.z + v0.w*v0.w
             + v1.x*v1.x + v1.y*v1.y + v1.z*v1.z + v1.w*v1.w;
    #pragma unroll
    for (int o = 16; o > 0; o >>= 1) {
        s  += __shfl_xor_sync(0xffffffffu, s, o);
        s2 += __shfl_xor_sync(0xffffffffu, s2, o);
    }
    float mean = s * (1.f / 256.f);
    float var  = s2 * (1.f / 256.f) - mean * mean;
    float rstd = rsqrtf(var + 1e-5f);
    const float4* gp = (const float4*)(g  + lane * 8);
    const float4* bp = (const float4*)(bb + lane * 8);
    float4 g0 = gp[0], g1 = gp[1], b0 = bp[0], b1 = bp[1];
    float4 o0, o1;
    o0.x = (v0.x - mean) * rstd * g0.x + b0.x;
    o0.y = (v0.y - mean) * rstd * g0.y + b0.y;
    o0.z = (v0.z - mean) * rstd * g0.z + b0.z;
    o0.w = (v0.w - mean) * rstd * g0.w + b0.w;
    o1.x = (v1.x - mean) * rstd * g1.x + b1.x;
    o1.y = (v1.y - mean) * rstd * g1.y + b1.y;
    o1.z = (v1.z - mean) * rstd * g1.z + b1.z;
    o1.w = (v1.w - mean) * rstd * g1.w + b1.w;
    float4* op = (float4*)(out + (long)r * C_DIM + lane * 8);
    op[0] = o0; op[1] = o1;
}

// ---------------------------------------------------------------------------
// TF32 tensor-core GEMM: C = epi(A[MxK] @ B[KxN] + bias)
// EPI 0: plain. 1: GELU. 2: scatter+residual -> hs AND fused LN2 -> Y.
// EPI 3: residual.   EPI==2 requires BN == N.
// R12: R10 mainloop structure (per-ks fragment loads, tail-position
// prefetch) with BK=32 / NSTG=3 — half the barriers per K.
// ---------------------------------------------------------------------------
#define NSTG 3
#define BM   128
#define BN   256
#define BK   32
#define ASTR 36
#define BSTR 264
#define A_STAGE (BM * ASTR)    // 4608 floats
#define B_STAGE (BK * BSTR)    // 8448 floats
#define SMEM_SZ ((NSTG * (A_STAGE + B_STAGE)) * 4)   // 156672 bytes

template<int EPI>
__global__ __launch_bounds__(256, 1) void tf32gemm(
    const float* __restrict__ A, const float* __restrict__ B,
    const float* __restrict__ bias, const float* __restrict__ R,
    float* __restrict__ C, int M, int N, int K,
    const float* __restrict__ G2, const float* __restrict__ B2,
    float* __restrict__ Y)
{
    extern __shared__ float sm[];
    float* Asm = sm;
    float* Bsm = sm + NSTG * A_STAGE;

    int tid  = threadIdx.x;
    int lane = tid & 31, warp = tid >> 5;
    int wm = warp >> 2, wn = warp & 3;
    int bm = blockIdx.y * BM, bn = blockIdx.x * BN;
    int gid = lane >> 2, tig = lane & 3;

    float acc[4][8][4];
    #pragma unroll
    for (int mt = 0; mt < 4; mt++)
        #pragma unroll
        for (int nt = 0; nt < 8; nt++)
            #pragma unroll
            for (int i = 0; i < 4; i++) acc[mt][nt][i] = 0.f;

    // A tile: 128x32 = 1024 float4 segs (4/thread); B: 32x256 = 2048 (8/thread)
    int aR[4], aC[4], bR[8], bC[8];
    #pragma unroll
    for (int i = 0; i < 4; i++) {
        int s = tid + i * 256;
        aR[i] = s >> 3;  aC[i] = (s & 7) * 4;
    }
    #pragma unroll
    for (int i = 0; i < 8; i++) {
        int s = tid + i * 256;
        bR[i] = s >> 6;  bC[i] = (s & 63) * 4;
    }

    int KT = K >> 5;

    #pragma unroll
    for (int s = 0; s < NSTG - 1; s++) {
        int kb = s << 5;
        float* as = Asm + s * A_STAGE;
        float* bs = Bsm + s * B_STAGE;
        #pragma unroll
        for (int i = 0; i < 4; i++)
            cp_async16(&as[aR[i] * ASTR + aC[i]], A + (long)(bm + aR[i]) * K + kb + aC[i]);
        #pragma unroll
        for (int i = 0; i < 8; i++)
            cp_async16(&bs[bR[i] * BSTR + bC[i]], B + (long)(kb + bR[i]) * N + bn + bC[i]);
        cp_commit();
    }

    for (int kt = 0; kt < KT; kt++) {
        if (kt + NSTG - 1 < KT) cp_wait<NSTG - 2>(); else cp_wait<0>();
        __syncthreads();
        int stg = kt % NSTG;
        const float* as = Asm + stg * A_STAGE;
        const float* bs = Bsm + stg * B_STAGE;
        #pragma unroll
        for (int ks = 0; ks < 4; ks++) {
            uint32_t af[4][4], bf[8][2];
            #pragma unroll
            for (int mt = 0; mt < 4; mt++) {
                int r0 = wm * 64 + mt * 16 + gid;
                int c0 = ks * 8 + tig;
                af[mt][0] = __float_as_uint(as[r0 * ASTR + c0]);
                af[mt][1] = __float_as_uint(as[(r0 + 8) * ASTR + c0]);
                af[mt][2] = __float_as_uint(as[r0 * ASTR + c0 + 4]);
                af[mt][3] = __float_as_uint(as[(r0 + 8) * ASTR + c0 + 4]);
            }
            #pragma unroll
            for (int nt = 0; nt < 8; nt++) {
                int rr = ks * 8 + tig;
                int cc = wn * 64 + nt * 8 + gid;
                bf[nt][0] = __float_as_uint(bs[rr * BSTR + cc]);
                bf[nt][1] = __float_as_uint(bs[(rr + 4) * BSTR + cc]);
            }
            #pragma unroll
            for (int mt = 0; mt < 4; mt++)
                #pragma unroll
                for (int nt = 0; nt < 8; nt++)
                    mma_tf32(acc[mt][nt], af[mt], bf[nt]);
        }
        if (kt + NSTG - 1 < KT) {
            int kn = kt + NSTG - 1;
            int kb = kn << 5;
            int ds = kn % NSTG;
            float* asn = Asm + ds * A_STAGE;
            float* bsn = Bsm + ds * B_STAGE;
            #pragma unroll
            for (int i = 0; i < 4; i++)
                cp_async16(&asn[aR[i] * ASTR + aC[i]], A + (long)(bm + aR[i]) * K + kb + aC[i]);
            #pragma unroll
            for (int i = 0; i < 8; i++)
                cp_async16(&bsn[bR[i] * BSTR + bC[i]], B + (long)(kb + bR[i]) * N + bn + bC[i]);
            cp_commit();
        }
    }

    if (EPI == 2) {
        // ---- fused: hs = GEMM + bias + residual (scattered), y = LN(hs) ----
        __syncthreads();                 // before reusing smem for reduction
        float* red = sm;                 // 128 rows x (4 warps x {sum,sq}) = 4KB
        long orows[4][2];
        float rsum[4][2], rsq[4][2];
        #pragma unroll
        for (int mt = 0; mt < 4; mt++) {
            #pragma unroll
            for (int half = 0; half < 2; half++) {
                int row = bm + wm * 64 + mt * 16 + half * 8 + gid;
                int b  = row >> 12;
                int wi = (row >> 9) & 7, wj = (row >> 6) & 7;
                int pi = (row >> 3) & 7, pj = row & 7;
                int h = (wi * 8 + pi + 4) & 63;
                int w = (wj * 8 + pj + 4) & 63;
                long orow = (long)b * 4096 + h * 64 + w;
                orows[mt][half] = orow;
                float s = 0.f, q = 0.f;
                #pragma unroll
                for (int nt = 0; nt < 8; nt++) {
                    int col = bn + wn * 64 + nt * 8 + 2 * tig;
                    float v0 = acc[mt][nt][half * 2 + 0] + bias[col];
                    float v1 = acc[mt][nt][half * 2 + 1] + bias[col + 1];
                    float2 rr = *(const float2*)(R + orow * N + col);
                    v0 += rr.x; v1 += rr.y;
                    acc[mt][nt][half * 2 + 0] = v0;
                    acc[mt][nt][half * 2 + 1] = v1;
                    s += v0 + v1;
                    q += v0 * v0 + v1 * v1;
                    float2 o; o.x = v0; o.y = v1;
                    *(float2*)(C + orow * N + col) = o;
                }
                rsum[mt][half] = s; rsq[mt][half] = q;
            }
        }
        #pragma unroll
        for (int mt = 0; mt < 4; mt++) {
            #pragma unroll
            for (int half = 0; half < 2; half++) {
                float s = rsum[mt][half], q = rsq[mt][half];
                s += __shfl_xor_sync(0xffffffffu, s, 1);
                q += __shfl_xor_sync(0xffffffffu, q, 1);
                s += __shfl_xor_sync(0xffffffffu, s, 2);
                q += __shfl_xor_sync(0xffffffffu, q, 2);
                if (tig == 0) {
                    int lr = wm * 64 + mt * 16 + half * 8 + gid;
                    red[lr * 8 + wn * 2]     = s;
                    red[lr * 8 + wn * 2 + 1] = q;
                }
            }
        }
        __syncthreads();
        #pragma unroll
        for (int mt = 0; mt < 4; mt++) {
            #pragma unroll
            for (int half = 0; half < 2; half++) {
                int lr = wm * 64 + mt * 16 + half * 8 + gid;
                float s = red[lr*8+0] + red[lr*8+2] + red[lr*8+4] + red[lr*8+6];
                float q = red[lr*8+1] + red[lr*8+3] + red[lr*8+5] + red[lr*8+7];
                float mean = s * (1.f / 256.f);
                float var  = q * (1.f / 256.f) - mean * mean;
                float rstd = rsqrtf(var + 1e-5f);
                long orow = orows[mt][half];
                #pragma unroll
                for (int nt = 0; nt < 8; nt++) {
                    int col = bn + wn * 64 + nt * 8 + 2 * tig;
                    float v0 = acc[mt][nt][half * 2 + 0];
                    float v1 = acc[mt][nt][half * 2 + 1];
                    float2 o;
                    o.x = (v0 - mean) * rstd * G2[col]     + B2[col];
                    o.y = (v1 - mean) * rstd * G2[col + 1] + B2[col + 1];
                    *(float2*)(Y + orow * N + col) = o;
                }
            }
        }
        return;
    }

    // ---- standard epilogues (EPI 0, 1, 3) ----
    #pragma unroll
    for (int mt = 0; mt < 4; mt++) {
        #pragma unroll
        for (int half = 0; half < 2; half++) {
            int row = bm + wm * 64 + mt * 16 + half * 8 + gid;
            long orow = row;
            #pragma unroll
            for (int nt = 0; nt < 8; nt++) {
                int col = bn + wn * 64 + nt * 8 + 2 * tig;
                float v0 = acc[mt][nt][half * 2 + 0] + bias[col];
                float v1 = acc[mt][nt][half * 2 + 1] + bias[col + 1];
                if (EPI == 1) {
                    v0 = 0.5f * v0 * (1.f + erff(v0 * 0.70710678118654752f));
                    v1 = 0.5f * v1 * (1.f + erff(v1 * 0.70710678118654752f));
                }
                if (EPI == 3) {
                    float2 rr = *(const float2*)(R + orow * N + col);
                    v0 += rr.x; v1 += rr.y;
                }
                float2 o; o.x = v0; o.y = v1;
                *(float2*)(C + orow * N + col) = o;
            }
        }
    }
}

// ---------------------------------------------------------------------------
// Tensor-core windowed attention, 1xTF32 (direct fp32-bit fragments).
// One block = one (window, head), 128 threads / 4 warps.
// Conflict-free strides: Q/K 36, V 40, P 68.
// ---------------------------------------------------------------------------
#define QSTR 36
#define VSTR 40
#define PSTR 68

__device__ __forceinline__ int bandf(int z) { return z < 56 ? 0 : (z < 60 ? 1 : 2); }

__global__ __launch_bounds__(128) void attn_kernel(
    const float* __restrict__ QKV, const float* __restrict__ bt,
    float* __restrict__ O)
{
    __shared__ float Qs[64 * QSTR];
    __shared__ float Ks[64 * QSTR];
    __shared__ float Vs[64 * VSTR];
    __shared__ float Ps[64 * PSTR];
    __shared__ float btS[228];

    int win  = blockIdx.x;
    int head = blockIdx.y;
    int t = threadIdx.x;
    int warp = t >> 5, lane = t & 31;
    int gid = lane >> 2, tig = lane & 3;
    long base = (long)win * 64 * 768 + head * 32;

    for (int i = t; i < 225; i += 128) btS[i] = bt[i * 8 + head];

    const float scale = 0.17677669529663687f;   // 32^-0.5
    #pragma unroll
    for (int i = 0; i < 4; i++) {
        int idx = t + i * 128;
        int row = idx >> 3, c4 = (idx & 7) * 4;
        const float* src = QKV + base + (long)row * 768 + c4;
        float4 q = *(const float4*)(src);
        q.x *= scale; q.y *= scale; q.z *= scale; q.w *= scale;
        *(float4*)&Qs[row * QSTR + c4] = q;
        *(float4*)&Ks[row * QSTR + c4] = *(const float4*)(src + 256);
        *(float4*)&Vs[row * VSTR + c4] = *(const float4*)(src + 512);
    }
    __syncthreads();

    // ---- S = Q@K^T : warp covers key-cols [warp*16, warp*16+16) ----
    float sc[4][2][4];
    #pragma unroll
    for (int mt = 0; mt < 4; mt++)
        #pragma unroll
        for (int nt = 0; nt < 2; nt++)
            #pragma unroll
            for (int i = 0; i < 4; i++) sc[mt][nt][i] = 0.f;

    #pragma unroll
    for (int kt = 0; kt < 4; kt++) {
        uint32_t af[4][4], bf[2][2];
        #pragma unroll
        for (int mt = 0; mt < 4; mt++) {
            int r0 = mt * 16 + gid;
            int c0 = kt * 8 + tig;
            af[mt][0] = __float_as_uint(Qs[r0 * QSTR + c0]);
            af[mt][1] = __float_as_uint(Qs[(r0 + 8) * QSTR + c0]);
            af[mt][2] = __float_as_uint(Qs[r0 * QSTR + c0 + 4]);
            af[mt][3] = __float_as_uint(Qs[(r0 + 8) * QSTR + c0 + 4]);
        }
        #pragma unroll
        for (int nt = 0; nt < 2; nt++) {
            int kr = warp * 16 + nt * 8 + gid;
            int kc = kt * 8 + tig;
            bf[nt][0] = __float_as_uint(Ks[kr * QSTR + kc]);
            bf[nt][1] = __float_as_uint(Ks[kr * QSTR + kc + 4]);
        }
        #pragma unroll
        for (int mt = 0; mt < 4; mt++)
            #pragma unroll
            for (int nt = 0; nt < 2; nt++)
                mma_tf32(sc[mt][nt], af[mt], bf[nt]);
    }

    // ---- bias + shift mask, store S to Ps ----
    int w_in_b = win & 63;
    int wwi = w_in_b >> 3, wwj = w_in_b & 7;
    bool edge = (wwi == 7) || (wwj == 7);
    #pragma unroll
    for (int mt = 0; mt < 4; mt++) {
        #pragma unroll
        for (int half = 0; half < 2; half++) {
            int r = mt * 16 + half * 8 + gid;
            int yi = r >> 3, xi = r & 7;
            int id_i = edge ? bandf(wwi * 8 + yi) * 3 + bandf(wwj * 8 + xi) : 0;
            #pragma unroll
            for (int nt = 0; nt < 2; nt++) {
                int c0 = warp * 16 + nt * 8 + 2 * tig;
                float v0 = sc[mt][nt][half * 2 + 0];
                float v1 = sc[mt][nt][half * 2 + 1];
                #pragma unroll
                for (int j = 0; j < 2; j++) {
                    int c = c0 + j;
                    int yj = c >> 3, xj = c & 7;
                    float add = btS[(yi - yj + 7) * 15 + (xi - xj + 7)];
                    if (edge) {
                        int id_j = bandf(wwi * 8 + yj) * 3 + bandf(wwj * 8 + xj);
                        if (id_i != id_j) add -= 100.f;
                    }
                    if (j == 0) v0 += add; else v1 += add;
                }
                float2 st; st.x = v0; st.y = v1;
                *(float2*)&Ps[r * PSTR + c0] = st;
            }
        }
    }
    __syncthreads();

    // ---- softmax: thread handles half a row ----
    {
        int row = t >> 1;
        int c0 = (t & 1) * 32;
        float4 e[8];
        float mx = -1e30f;
        #pragma unroll
        for (int i = 0; i < 8; i++) {
            e[i] = *(const float4*)&Ps[row * PSTR + c0 + i * 4];
            mx = fmaxf(mx, fmaxf(fmaxf(e[i].x, e[i].y), fmaxf(e[i].z, e[i].w)));
        }
        mx = fmaxf(mx, __shfl_xor_sync(0xffffffffu, mx, 1));
        float sum = 0.f;
        #pragma unroll
        for (int i = 0; i < 8; i++) {
            e[i].x = __expf(e[i].x - mx); e[i].y = __expf(e[i].y - mx);
            e[i].z = __expf(e[i].z - mx); e[i].w = __expf(e[i].w - mx);
            sum += e[i].x + e[i].y + e[i].z + e[i].w;
        }
        sum += __shfl_xor_sync(0xffffffffu, sum, 1);
        float rs = 1.f / sum;
        #pragma unroll
        for (int i = 0; i < 8; i++) {
            e[i].x *= rs; e[i].y *= rs; e[i].z *= rs; e[i].w *= rs;
            *(float4*)&Ps[row * PSTR + c0 + i * 4] = e[i];
        }
    }
    __syncthreads();

    // ---- O = P@V : warp covers query-rows [warp*16, warp*16+16) ----
    float oc[4][4];
    #pragma unroll
    for (int nt = 0; nt < 4; nt++)
        #pragma unroll
        for (int i = 0; i < 4; i++) oc[nt][i] = 0.f;

    #pragma unroll
    for (int kt = 0; kt < 8; kt++) {
        uint32_t af[4], bf[4][2];
        int r0 = warp * 16 + gid;
        int c0 = kt * 8 + tig;
        af[0] = __float_as_uint(Ps[r0 * PSTR + c0]);
        af[1] = __float_as_uint(Ps[(r0 + 8) * PSTR + c0]);
        af[2] = __float_as_uint(Ps[r0 * PSTR + c0 + 4]);
        af[3] = __float_as_uint(Ps[(r0 + 8) * PSTR + c0 + 4]);
        #pragma unroll
        for (int nt = 0; nt < 4; nt++) {
            int vr = kt * 8 + tig;
            int vc = nt * 8 + gid;
            bf[nt][0] = __float_as_uint(Vs[vr * VSTR + vc]);
            bf[nt][1] = __float_as_uint(Vs[(vr + 4) * VSTR + vc]);
        }
        #pragma unroll
        for (int nt = 0; nt < 4; nt++)
            mma_tf32(oc[nt], af, bf[nt]);
    }

    // ---- write O ----
    long obase = ((long)win * 64) * C_DIM + head * 32;
    #pragma unroll
    for (int half = 0; half < 2; half++) {
        int row = warp * 16 + half * 8 + gid;
        #pragma unroll
        for (int nt = 0; nt < 4; nt++) {
            int col = nt * 8 + 2 * tig;
            float2 o;
            o.x = oc[nt][half * 2 + 0];
            o.y = oc[nt][half * 2 + 1];
            *(float2*)(O + obase + (long)row * C_DIM + col) = o;
        }
    }
}

// ---------------------------------------------------------------------------
// Launch
// ---------------------------------------------------------------------------
extern "C" void kernel_launch(void* const* d_in, const int* in_sizes, int n_in,
                              void* d_out, int out_size)
{
    const float* hidden = (const float*)d_in[0];
    const float* ln1_g  = (const float*)d_in[1];
    const float* ln1_b  = (const float*)d_in[2];
    const float* wq     = (const float*)d_in[3];
    const float* bq     = (const float*)d_in[4];
    const float* wk     = (const float*)d_in[5];
    const float* bk     = (const float*)d_in[6];
    const float* wv     = (const float*)d_in[7];
    const float* bv     = (const float*)d_in[8];
    const float* bt     = (const float*)d_in[9];
    const float* wo     = (const float*)d_in[10];
    const float* bo     = (const float*)d_in[11];
    const float* ln2_g  = (const float*)d_in[12];
    const float* ln2_b  = (const float*)d_in[13];
    const float* w1     = (const float*)d_in[14];
    const float* b1     = (const float*)d_in[15];
    const float* w2     = (const float*)d_in[16];
    const float* b2     = (const float*)d_in[17];
    float* out = (float*)d_out;

    float *p_xw, *p_qkv, *p_att, *p_hs, *p_y, *p_mid, *p_wqkv, *p_bqkv;
    cudaGetSymbolAddress((void**)&p_xw,   g_xw);
    cudaGetSymbolAddress((void**)&p_qkv,  g_qkv);
    cudaGetSymbolAddress((void**)&p_att,  g_att);
    cudaGetSymbolAddress((void**)&p_hs,   g_hs);
    cudaGetSymbolAddress((void**)&p_y,    g_y);
    cudaGetSymbolAddress((void**)&p_mid,  g_mid);
    cudaGetSymbolAddress((void**)&p_wqkv, g_wqkv);
    cudaGetSymbolAddress((void**)&p_bqkv, g_bqkv);

    cudaFuncSetAttribute(tf32gemm<0>, cudaFuncAttributeMaxDynamicSharedMemorySize, SMEM_SZ);
    cudaFuncSetAttribute(tf32gemm<1>, cudaFuncAttributeMaxDynamicSharedMemorySize, SMEM_SZ);
    cudaFuncSetAttribute(tf32gemm<2>, cudaFuncAttributeMaxDynamicSharedMemorySize, SMEM_SZ);
    cudaFuncSetAttribute(tf32gemm<3>, cudaFuncAttributeMaxDynamicSharedMemorySize, SMEM_SZ);

    dim3 blk(256);

    pack_qkv<<<768, blk>>>(wq, wk, wv, bq, bk, bv, p_wqkv, p_bqkv);
    ln_kernel<<<M_TOK / 8, blk>>>(hidden, ln1_g, ln1_b, p_xw, 1);
    tf32gemm<0><<<dim3(768 / BN, M_TOK / BM), blk, SMEM_SZ>>>(
        p_xw, p_wqkv, p_bqkv, nullptr, p_qkv, M_TOK, 768, C_DIM,
        nullptr, nullptr, nullptr);
    attn_kernel<<<dim3(2048, 8), dim3(128)>>>(p_qkv, bt, p_att);
    // wo-projection + scatter + residual -> hs, fused LN2 -> y
    tf32gemm<2><<<dim3(C_DIM / BN, M_TOK / BM), blk, SMEM_SZ>>>(
        p_att, wo, bo, hidden, p_hs, M_TOK, C_DIM, C_DIM,
        ln2_g, ln2_b, p_y);
    tf32gemm<1><<<dim3(DFF / BN, M_TOK / BM), blk, SMEM_SZ>>>(
        p_y, w1, b1, nullptr, p_mid, M_TOK, DFF, C_DIM,
        nullptr, nullptr, nullptr);
    tf32gemm<3><<<dim3(C_DIM / BN, M_TOK / BM), blk, SMEM_SZ>>>(
        p_mid, w2, b2, p_hs, out, M_TOK, C_DIM, DFF,
        nullptr, nullptr, nullptr);
}

// round 14
// speedup vs baseline: 1.1865x; 1.0513x over previous
#include <cuda_runtime.h>
#include <math.h>
#include <stdint.h>

// ---------------------------------------------------------------------------
// Problem constants: B=32, H=W=64, C=256, NH=8, hd=32, WS=8, SS=4, IM=4
// ---------------------------------------------------------------------------
#define M_TOK   131072
#define C_DIM   256
#define DFF     1024

// Scratch (device globals; no allocation at runtime)
__device__ float g_xw   [M_TOK * C_DIM];
__device__ float g_qkv  [M_TOK * 768];
__device__ float g_att  [M_TOK * C_DIM];
__device__ float g_hs   [M_TOK * C_DIM];
__device__ float g_y    [M_TOK * C_DIM];
__device__ float g_mid  [M_TOK * DFF];
__device__ float g_wqkv [C_DIM * 768];
__device__ float g_bqkv [768];

// ---------------------------------------------------------------------------
// cp.async helpers
// ---------------------------------------------------------------------------
__device__ __forceinline__ void cp_async16(void* smem, const void* gmem) {
    uint32_t s = (uint32_t)__cvta_generic_to_shared(smem);
    asm volatile("cp.async.cg.shared.global [%0], [%1], 16;\n" :: "r"(s), "l"(gmem));
}
__device__ __forceinline__ void cp_commit() {
    asm volatile("cp.async.commit_group;\n");
}
template<int N>
__device__ __forceinline__ void cp_wait() {
    asm volatile("cp.async.wait_group %0;\n" :: "n"(N));
}

__device__ __forceinline__ void mma_tf32(float d[4], const uint32_t a[4], const uint32_t b[2]) {
    asm volatile(
        "mma.sync.aligned.m16n8k8.row.col.f32.tf32.tf32.f32 "
        "{%0,%1,%2,%3}, {%4,%5,%6,%7}, {%8,%9}, {%0,%1,%2,%3};\n"
        : "+f"(d[0]), "+f"(d[1]), "+f"(d[2]), "+f"(d[3])
        : "r"(a[0]), "r"(a[1]), "r"(a[2]), "r"(a[3]), "r"(b[0]), "r"(b[1]));
}

// ---------------------------------------------------------------------------
// Pack wq|wk|wv -> [256,768], bq|bk|bv -> [768]
// ---------------------------------------------------------------------------
__global__ __launch_bounds__(256) void pack_qkv(
    const float* __restrict__ wq, const float* __restrict__ wk,
    const float* __restrict__ wv, const float* __restrict__ bq,
    const float* __restrict__ bk, const float* __restrict__ bv,
    float* __restrict__ wdst, float* __restrict__ bdst)
{
    int idx = blockIdx.x * 256 + threadIdx.x;
    int k = idx / 768, n = idx % 768;
    float v = (n < 256) ? wq[k * 256 + n]
            : (n < 512) ? wk[k * 256 + n - 256]
                        : wv[k * 256 + n - 512];
    wdst[idx] = v;
    if (idx < 768)
        bdst[idx] = (idx < 256) ? bq[idx] : (idx < 512) ? bk[idx - 256] : bv[idx - 512];
}

// ---------------------------------------------------------------------------
// LayerNorm: warp-per-token, 8 tokens/block, float4 I/O. (LN1 only)
// ---------------------------------------------------------------------------
__global__ __launch_bounds__(256) void ln_kernel(
    const float* __restrict__ x, const float* __restrict__ g,
    const float* __restrict__ bb, float* __restrict__ out, int gather)
{
    int warp = threadIdx.x >> 5, lane = threadIdx.x & 31;
    int r = blockIdx.x * 8 + warp;
    long src;
    if (gather) {
        int b  = r >> 12;
        int wi = (r >> 9) & 7, wj = (r >> 6) & 7;
        int pi = (r >> 3) & 7, pj = r & 7;
        int h = (wi * 8 + pi + 4) & 63;
        int w = (wj * 8 + pj + 4) & 63;
        src = (long)b * 4096 + h * 64 + w;
    } else {
        src = r;
    }
    const float4* xp = (const float4*)(x + src * C_DIM);
    float4 v0 = xp[lane * 2], v1 = xp[lane * 2 + 1];
    float s  = v0.x + v0.y + v0.z + v0.w + v1.x + v1.y + v1.z + v1.w;
    float s2 = v0.x*v0.x + v0.y*v0.y + v0.z*v0.z + v0.w*v0.w
             + v1.x*v1.x + v1.y*v1.y + v1.z*v1.z + v1.w*v1.w;
    #pragma unroll
    for (int o = 16; o > 0; o >>= 1) {
        s  += __shfl_xor_sync(0xffffffffu, s, o);
        s2 += __shfl_xor_sync(0xffffffffu, s2, o);
    }
    float mean = s * (1.f / 256.f);
    float var  = s2 * (1.f / 256.f) - mean * mean;
    float rstd = rsqrtf(var + 1e-5f);
    const float4* gp = (const float4*)(g  + lane * 8);
    const float4* bp = (const float4*)(bb + lane * 8);
    float4 g0 = gp[0], g1 = gp[1], b0 = bp[0], b1 = bp[1];
    float4 o0, o1;
    o0.x = (v0.x - mean) * rstd * g0.x + b0.x;
    o0.y = (v0.y - mean) * rstd * g0.y + b0.y;
    o0.z = (v0.z - mean) * rstd * g0.z + b0.z;
    o0.w = (v0.w - mean) * rstd * g0.w + b0.w;
    o1.x = (v1.x - mean) * rstd * g1.x + b1.x;
    o1.y = (v1.y - mean) * rstd * g1.y + b1.y;
    o1.z = (v1.z - mean) * rstd * g1.z + b1.z;
    o1.w = (v1.w - mean) * rstd * g1.w + b1.w;
    float4* op = (float4*)(out + (long)r * C_DIM + lane * 8);
    op[0] = o0; op[1] = o1;
}

// ===========================================================================
// BIG-TILE GEMM (128x256, 1 CTA/SM) — used ONLY for EPI==2 (wo + fused LN2,
// which needs BN == N).
// ===========================================================================
#define NSTG 3
#define BM   128
#define BN   256
#define BK   32
#define ASTR 36
#define BSTR 264
#define A_STAGE (BM * ASTR)
#define B_STAGE (BK * BSTR)
#define SMEM_SZ ((NSTG * (A_STAGE + B_STAGE)) * 4)

template<int EPI>
__global__ __launch_bounds__(256, 1) void tf32gemm(
    const float* __restrict__ A, const float* __restrict__ B,
    const float* __restrict__ bias, const float* __restrict__ R,
    float* __restrict__ C, int M, int N, int K,
    const float* __restrict__ G2, const float* __restrict__ B2,
    float* __restrict__ Y)
{
    extern __shared__ float sm[];
    float* Asm = sm;
    float* Bsm = sm + NSTG * A_STAGE;

    int tid  = threadIdx.x;
    int lane = tid & 31, warp = tid >> 5;
    int wm = warp >> 2, wn = warp & 3;
    int bm = blockIdx.y * BM, bn = blockIdx.x * BN;
    int gid = lane >> 2, tig = lane & 3;

    float acc[4][8][4];
    #pragma unroll
    for (int mt = 0; mt < 4; mt++)
        #pragma unroll
        for (int nt = 0; nt < 8; nt++)
            #pragma unroll
            for (int i = 0; i < 4; i++) acc[mt][nt][i] = 0.f;

    int aR[4], aC[4], bR[8], bC[8];
    #pragma unroll
    for (int i = 0; i < 4; i++) {
        int s = tid + i * 256;
        aR[i] = s >> 3;  aC[i] = (s & 7) * 4;
    }
    #pragma unroll
    for (int i = 0; i < 8; i++) {
        int s = tid + i * 256;
        bR[i] = s >> 6;  bC[i] = (s & 63) * 4;
    }

    int KT = K >> 5;

    #pragma unroll
    for (int s = 0; s < NSTG - 1; s++) {
        int kb = s << 5;
        float* as = Asm + s * A_STAGE;
        float* bs = Bsm + s * B_STAGE;
        #pragma unroll
        for (int i = 0; i < 4; i++)
            cp_async16(&as[aR[i] * ASTR + aC[i]], A + (long)(bm + aR[i]) * K + kb + aC[i]);
        #pragma unroll
        for (int i = 0; i < 8; i++)
            cp_async16(&bs[bR[i] * BSTR + bC[i]], B + (long)(kb + bR[i]) * N + bn + bC[i]);
        cp_commit();
    }

    for (int kt = 0; kt < KT; kt++) {
        if (kt + NSTG - 1 < KT) cp_wait<NSTG - 2>(); else cp_wait<0>();
        __syncthreads();
        int stg = kt % NSTG;
        const float* as = Asm + stg * A_STAGE;
        const float* bs = Bsm + stg * B_STAGE;
        #pragma unroll
        for (int ks = 0; ks < 4; ks++) {
            uint32_t af[4][4], bf[8][2];
            #pragma unroll
            for (int mt = 0; mt < 4; mt++) {
                int r0 = wm * 64 + mt * 16 + gid;
                int c0 = ks * 8 + tig;
                af[mt][0] = __float_as_uint(as[r0 * ASTR + c0]);
                af[mt][1] = __float_as_uint(as[(r0 + 8) * ASTR + c0]);
                af[mt][2] = __float_as_uint(as[r0 * ASTR + c0 + 4]);
                af[mt][3] = __float_as_uint(as[(r0 + 8) * ASTR + c0 + 4]);
            }
            #pragma unroll
            for (int nt = 0; nt < 8; nt++) {
                int rr = ks * 8 + tig;
                int cc = wn * 64 + nt * 8 + gid;
                bf[nt][0] = __float_as_uint(bs[rr * BSTR + cc]);
                bf[nt][1] = __float_as_uint(bs[(rr + 4) * BSTR + cc]);
            }
            #pragma unroll
            for (int mt = 0; mt < 4; mt++)
                #pragma unroll
                for (int nt = 0; nt < 8; nt++)
                    mma_tf32(acc[mt][nt], af[mt], bf[nt]);
        }
        if (kt + NSTG - 1 < KT) {
            int kn = kt + NSTG - 1;
            int kb = kn << 5;
            int ds = kn % NSTG;
            float* asn = Asm + ds * A_STAGE;
            float* bsn = Bsm + ds * B_STAGE;
            #pragma unroll
            for (int i = 0; i < 4; i++)
                cp_async16(&asn[aR[i] * ASTR + aC[i]], A + (long)(bm + aR[i]) * K + kb + aC[i]);
            #pragma unroll
            for (int i = 0; i < 8; i++)
                cp_async16(&bsn[bR[i] * BSTR + bC[i]], B + (long)(kb + bR[i]) * N + bn + bC[i]);
            cp_commit();
        }
    }

    if (EPI == 2) {
        // ---- fused: hs = GEMM + bias + residual (scattered), y = LN(hs) ----
        __syncthreads();
        float* red = sm;
        long orows[4][2];
        float rsum[4][2], rsq[4][2];
        #pragma unroll
        for (int mt = 0; mt < 4; mt++) {
            #pragma unroll
            for (int half = 0; half < 2; half++) {
                int row = bm + wm * 64 + mt * 16 + half * 8 + gid;
                int b  = row >> 12;
                int wi = (row >> 9) & 7, wj = (row >> 6) & 7;
                int pi = (row >> 3) & 7, pj = row & 7;
                int h = (wi * 8 + pi + 4) & 63;
                int w = (wj * 8 + pj + 4) & 63;
                long orow = (long)b * 4096 + h * 64 + w;
                orows[mt][half] = orow;
                float s = 0.f, q = 0.f;
                #pragma unroll
                for (int nt = 0; nt < 8; nt++) {
                    int col = bn + wn * 64 + nt * 8 + 2 * tig;
                    float v0 = acc[mt][nt][half * 2 + 0] + bias[col];
                    float v1 = acc[mt][nt][half * 2 + 1] + bias[col + 1];
                    float2 rr = *(const float2*)(R + orow * N + col);
                    v0 += rr.x; v1 += rr.y;
                    acc[mt][nt][half * 2 + 0] = v0;
                    acc[mt][nt][half * 2 + 1] = v1;
                    s += v0 + v1;
                    q += v0 * v0 + v1 * v1;
                    float2 o; o.x = v0; o.y = v1;
                    *(float2*)(C + orow * N + col) = o;
                }
                rsum[mt][half] = s; rsq[mt][half] = q;
            }
        }
        #pragma unroll
        for (int mt = 0; mt < 4; mt++) {
            #pragma unroll
            for (int half = 0; half < 2; half++) {
                float s = rsum[mt][half], q = rsq[mt][half];
                s += __shfl_xor_sync(0xffffffffu, s, 1);
                q += __shfl_xor_sync(0xffffffffu, q, 1);
                s += __shfl_xor_sync(0xffffffffu, s, 2);
                q += __shfl_xor_sync(0xffffffffu, q, 2);
                if (tig == 0) {
                    int lr = wm * 64 + mt * 16 + half * 8 + gid;
                    red[lr * 8 + wn * 2]     = s;
                    red[lr * 8 + wn * 2 + 1] = q;
                }
            }
        }
        __syncthreads();
        #pragma unroll
        for (int mt = 0; mt < 4; mt++) {
            #pragma unroll
            for (int half = 0; half < 2; half++) {
                int lr = wm * 64 + mt * 16 + half * 8 + gid;
                float s = red[lr*8+0] + red[lr*8+2] + red[lr*8+4] + red[lr*8+6];
                float q = red[lr*8+1] + red[lr*8+3] + red[lr*8+5] + red[lr*8+7];
                float mean = s * (1.f / 256.f);
                float var  = q * (1.f / 256.f) - mean * mean;
                float rstd = rsqrtf(var + 1e-5f);
                long orow = orows[mt][half];
                #pragma unroll
                for (int nt = 0; nt < 8; nt++) {
                    int col = bn + wn * 64 + nt * 8 + 2 * tig;
                    float v0 = acc[mt][nt][half * 2 + 0];
                    float v1 = acc[mt][nt][half * 2 + 1];
                    float2 o;
                    o.x = (v0 - mean) * rstd * G2[col]     + B2[col];
                    o.y = (v1 - mean) * rstd * G2[col + 1] + B2[col + 1];
                    *(float2*)(Y + orow * N + col) = o;
                }
            }
        }
        return;
    }
}

// ===========================================================================
// SMALL-TILE GEMM (128x128, 2 CTAs/SM) — EPI 0 plain, 1 GELU, 3 residual.
// 8 warps as 2(m) x 4(n), warp tile 64x32, acc = 64 regs.
// ===========================================================================
#define SBN     128
#define SBSTR   136            // 128+8; mod 32 = 8 -> conflict-free frags
#define SB_STAGE (BK * SBSTR)  // 4352 floats
#define SMEM_S  ((NSTG * (A_STAGE + SB_STAGE)) * 4)   // 107520 bytes

template<int EPI>
__global__ __launch_bounds__(256, 2) void tf32gemm_s(
    const float* __restrict__ A, const float* __restrict__ B,
    const float* __restrict__ bias, const float* __restrict__ R,
    float* __restrict__ C, int M, int N, int K)
{
    extern __shared__ float sm[];
    float* Asm = sm;
    float* Bsm = sm + NSTG * A_STAGE;

    int tid  = threadIdx.x;
    int lane = tid & 31, warp = tid >> 5;
    int wm = warp >> 2, wn = warp & 3;
    int bm = blockIdx.y * BM, bn = blockIdx.x * SBN;
    int gid = lane >> 2, tig = lane & 3;

    float acc[4][4][4];
    #pragma unroll
    for (int mt = 0; mt < 4; mt++)
        #pragma unroll
        for (int nt = 0; nt < 4; nt++)
            #pragma unroll
            for (int i = 0; i < 4; i++) acc[mt][nt][i] = 0.f;

    // A: 128x32 = 1024 segs (4/thread); B: 32x128 = 1024 segs (4/thread)
    int aR[4], aC[4], bR[4], bC[4];
    #pragma unroll
    for (int i = 0; i < 4; i++) {
        int s = tid + i * 256;
        aR[i] = s >> 3;  aC[i] = (s & 7) * 4;
        bR[i] = s >> 5;  bC[i] = (s & 31) * 4;
    }

    int KT = K >> 5;

    #pragma unroll
    for (int s = 0; s < NSTG - 1; s++) {
        int kb = s << 5;
        float* as = Asm + s * A_STAGE;
        float* bs = Bsm + s * SB_STAGE;
        #pragma unroll
        for (int i = 0; i < 4; i++) {
            cp_async16(&as[aR[i] * ASTR + aC[i]], A + (long)(bm + aR[i]) * K + kb + aC[i]);
            cp_async16(&bs[bR[i] * SBSTR + bC[i]], B + (long)(kb + bR[i]) * N + bn + bC[i]);
        }
        cp_commit();
    }

    for (int kt = 0; kt < KT; kt++) {
        if (kt + NSTG - 1 < KT) cp_wait<NSTG - 2>(); else cp_wait<0>();
        __syncthreads();
        int stg = kt % NSTG;
        const float* as = Asm + stg * A_STAGE;
        const float* bs = Bsm + stg * SB_STAGE;
        #pragma unroll
        for (int ks = 0; ks < 4; ks++) {
            uint32_t af[4][4], bf[4][2];
            #pragma unroll
            for (int mt = 0; mt < 4; mt++) {
                int r0 = wm * 64 + mt * 16 + gid;
                int c0 = ks * 8 + tig;
                af[mt][0] = __float_as_uint(as[r0 * ASTR + c0]);
                af[mt][1] = __float_as_uint(as[(r0 + 8) * ASTR + c0]);
                af[mt][2] = __float_as_uint(as[r0 * ASTR + c0 + 4]);
                af[mt][3] = __float_as_uint(as[(r0 + 8) * ASTR + c0 + 4]);
            }
            #pragma unroll
            for (int nt = 0; nt < 4; nt++) {
                int rr = ks * 8 + tig;
                int cc = wn * 32 + nt * 8 + gid;
                bf[nt][0] = __float_as_uint(bs[rr * SBSTR + cc]);
                bf[nt][1] = __float_as_uint(bs[(rr + 4) * SBSTR + cc]);
            }
            #pragma unroll
            for (int mt = 0; mt < 4; mt++)
                #pragma unroll
                for (int nt = 0; nt < 4; nt++)
                    mma_tf32(acc[mt][nt], af[mt], bf[nt]);
        }
        if (kt + NSTG - 1 < KT) {
            int kn = kt + NSTG - 1;
            int kb = kn << 5;
            int ds = kn % NSTG;
            float* asn = Asm + ds * A_STAGE;
            float* bsn = Bsm + ds * SB_STAGE;
            #pragma unroll
            for (int i = 0; i < 4; i++) {
                cp_async16(&asn[aR[i] * ASTR + aC[i]], A + (long)(bm + aR[i]) * K + kb + aC[i]);
                cp_async16(&bsn[bR[i] * SBSTR + bC[i]], B + (long)(kb + bR[i]) * N + bn + bC[i]);
            }
            cp_commit();
        }
    }

    #pragma unroll
    for (int mt = 0; mt < 4; mt++) {
        #pragma unroll
        for (int half = 0; half < 2; half++) {
            int row = bm + wm * 64 + mt * 16 + half * 8 + gid;
            #pragma unroll
            for (int nt = 0; nt < 4; nt++) {
                int col = bn + wn * 32 + nt * 8 + 2 * tig;
                float v0 = acc[mt][nt][half * 2 + 0] + bias[col];
                float v1 = acc[mt][nt][half * 2 + 1] + bias[col + 1];
                if (EPI == 1) {
                    v0 = 0.5f * v0 * (1.f + erff(v0 * 0.70710678118654752f));
                    v1 = 0.5f * v1 * (1.f + erff(v1 * 0.70710678118654752f));
                }
                if (EPI == 3) {
                    float2 rr = *(const float2*)(R + (long)row * N + col);
                    v0 += rr.x; v1 += rr.y;
                }
                float2 o; o.x = v0; o.y = v1;
                *(float2*)(C + (long)row * N + col) = o;
            }
        }
    }
}

// ---------------------------------------------------------------------------
// Tensor-core windowed attention, 1xTF32 (unchanged from R12).
// ---------------------------------------------------------------------------
#define QSTR 36
#define VSTR 40
#define PSTR 68

__device__ __forceinline__ int bandf(int z) { return z < 56 ? 0 : (z < 60 ? 1 : 2); }

__global__ __launch_bounds__(128) void attn_kernel(
    const float* __restrict__ QKV, const float* __restrict__ bt,
    float* __restrict__ O)
{
    __shared__ float Qs[64 * QSTR];
    __shared__ float Ks[64 * QSTR];
    __shared__ float Vs[64 * VSTR];
    __shared__ float Ps[64 * PSTR];
    __shared__ float btS[228];

    int win  = blockIdx.x;
    int head = blockIdx.y;
    int t = threadIdx.x;
    int warp = t >> 5, lane = t & 31;
    int gid = lane >> 2, tig = lane & 3;
    long base = (long)win * 64 * 768 + head * 32;

    for (int i = t; i < 225; i += 128) btS[i] = bt[i * 8 + head];

    const float scale = 0.17677669529663687f;
    #pragma unroll
    for (int i = 0; i < 4; i++) {
        int idx = t + i * 128;
        int row = idx >> 3, c4 = (idx & 7) * 4;
        const float* src = QKV + base + (long)row * 768 + c4;
        float4 q = *(const float4*)(src);
        q.x *= scale; q.y *= scale; q.z *= scale; q.w *= scale;
        *(float4*)&Qs[row * QSTR + c4] = q;
        *(float4*)&Ks[row * QSTR + c4] = *(const float4*)(src + 256);
        *(float4*)&Vs[row * VSTR + c4] = *(const float4*)(src + 512);
    }
    __syncthreads();

    float sc[4][2][4];
    #pragma unroll
    for (int mt = 0; mt < 4; mt++)
        #pragma unroll
        for (int nt = 0; nt < 2; nt++)
            #pragma unroll
            for (int i = 0; i < 4; i++) sc[mt][nt][i] = 0.f;

    #pragma unroll
    for (int kt = 0; kt < 4; kt++) {
        uint32_t af[4][4], bf[2][2];
        #pragma unroll
        for (int mt = 0; mt < 4; mt++) {
            int r0 = mt * 16 + gid;
            int c0 = kt * 8 + tig;
            af[mt][0] = __float_as_uint(Qs[r0 * QSTR + c0]);
            af[mt][1] = __float_as_uint(Qs[(r0 + 8) * QSTR + c0]);
            af[mt][2] = __float_as_uint(Qs[r0 * QSTR + c0 + 4]);
            af[mt][3] = __float_as_uint(Qs[(r0 + 8) * QSTR + c0 + 4]);
        }
        #pragma unroll
        for (int nt = 0; nt < 2; nt++) {
            int kr = warp * 16 + nt * 8 + gid;
            int kc = kt * 8 + tig;
            bf[nt][0] = __float_as_uint(Ks[kr * QSTR + kc]);
            bf[nt][1] = __float_as_uint(Ks[kr * QSTR + kc + 4]);
        }
        #pragma unroll
        for (int mt = 0; mt < 4; mt++)
            #pragma unroll
            for (int nt = 0; nt < 2; nt++)
                mma_tf32(sc[mt][nt], af[mt], bf[nt]);
    }

    int w_in_b = win & 63;
    int wwi = w_in_b >> 3, wwj = w_in_b & 7;
    bool edge = (wwi == 7) || (wwj == 7);
    #pragma unroll
    for (int mt = 0; mt < 4; mt++) {
        #pragma unroll
        for (int half = 0; half < 2; half++) {
            int r = mt * 16 + half * 8 + gid;
            int yi = r >> 3, xi = r & 7;
            int id_i = edge ? bandf(wwi * 8 + yi) * 3 + bandf(wwj * 8 + xi) : 0;
            #pragma unroll
            for (int nt = 0; nt < 2; nt++) {
                int c0 = warp * 16 + nt * 8 + 2 * tig;
                float v0 = sc[mt][nt][half * 2 + 0];
                float v1 = sc[mt][nt][half * 2 + 1];
                #pragma unroll
                for (int j = 0; j < 2; j++) {
                    int c = c0 + j;
                    int yj = c >> 3, xj = c & 7;
                    float add = btS[(yi - yj + 7) * 15 + (xi - xj + 7)];
                    if (edge) {
                        int id_j = bandf(wwi * 8 + yj) * 3 + bandf(wwj * 8 + xj);
                        if (id_i != id_j) add -= 100.f;
                    }
                    if (j == 0) v0 += add; else v1 += add;
                }
                float2 st; st.x = v0; st.y = v1;
                *(float2*)&Ps[r * PSTR + c0] = st;
            }
        }
    }
    __syncthreads();

    {
        int row = t >> 1;
        int c0 = (t & 1) * 32;
        float4 e[8];
        float mx = -1e30f;
        #pragma unroll
        for (int i = 0; i < 8; i++) {
            e[i] = *(const float4*)&Ps[row * PSTR + c0 + i * 4];
            mx = fmaxf(mx, fmaxf(fmaxf(e[i].x, e[i].y), fmaxf(e[i].z, e[i].w)));
        }
        mx = fmaxf(mx, __shfl_xor_sync(0xffffffffu, mx, 1));
        float sum = 0.f;
        #pragma unroll
        for (int i = 0; i < 8; i++) {
            e[i].x = __expf(e[i].x - mx); e[i].y = __expf(e[i].y - mx);
            e[i].z = __expf(e[i].z - mx); e[i].w = __expf(e[i].w - mx);
            sum += e[i].x + e[i].y + e[i].z + e[i].w;
        }
        sum += __shfl_xor_sync(0xffffffffu, sum, 1);
        float rs = 1.f / sum;
        #pragma unroll
        for (int i = 0; i < 8; i++) {
            e[i].x *= rs; e[i].y *= rs; e[i].z *= rs; e[i].w *= rs;
            *(float4*)&Ps[row * PSTR + c0 + i * 4] = e[i];
        }
    }
    __syncthreads();

    float oc[4][4];
    #pragma unroll
    for (int nt = 0; nt < 4; nt++)
        #pragma unroll
        for (int i = 0; i < 4; i++) oc[nt][i] = 0.f;

    #pragma unroll
    for (int kt = 0; kt < 8; kt++) {
        uint32_t af[4], bf[4][2];
        int r0 = warp * 16 + gid;
        int c0 = kt * 8 + tig;
        af[0] = __float_as_uint(Ps[r0 * PSTR + c0]);
        af[1] = __float_as_uint(Ps[(r0 + 8) * PSTR + c0]);
        af[2] = __float_as_uint(Ps[r0 * PSTR + c0 + 4]);
        af[3] = __float_as_uint(Ps[(r0 + 8) * PSTR + c0 + 4]);
        #pragma unroll
        for (int nt = 0; nt < 4; nt++) {
            int vr = kt * 8 + tig;
            int vc = nt * 8 + gid;
            bf[nt][0] = __float_as_uint(Vs[vr * VSTR + vc]);
            bf[nt][1] = __float_as_uint(Vs[(vr + 4) * VSTR + vc]);
        }
        #pragma unroll
        for (int nt = 0; nt < 4; nt++)
            mma_tf32(oc[nt], af, bf[nt]);
    }

    long obase = ((long)win * 64) * C_DIM + head * 32;
    #pragma unroll
    for (int half = 0; half < 2; half++) {
        int row = warp * 16 + half * 8 + gid;
        #pragma unroll
        for (int nt = 0; nt < 4; nt++) {
            int col = nt * 8 + 2 * tig;
            float2 o;
            o.x = oc[nt][half * 2 + 0];
            o.y = oc[nt][half * 2 + 1];
            *(float2*)(O + obase + (long)row * C_DIM + col) = o;
        }
    }
}

// ---------------------------------------------------------------------------
// Launch
// ---------------------------------------------------------------------------
extern "C" void kernel_launch(void* const* d_in, const int* in_sizes, int n_in,
                              void* d_out, int out_size)
{
    const float* hidden = (const float*)d_in[0];
    const float* ln1_g  = (const float*)d_in[1];
    const float* ln1_b  = (const float*)d_in[2];
    const float* wq     = (const float*)d_in[3];
    const float* bq     = (const float*)d_in[4];
    const float* wk     = (const float*)d_in[5];
    const float* bk     = (const float*)d_in[6];
    const float* wv     = (const float*)d_in[7];
    const float* bv     = (const float*)d_in[8];
    const float* bt     = (const float*)d_in[9];
    const float* wo     = (const float*)d_in[10];
    const float* bo     = (const float*)d_in[11];
    const float* ln2_g  = (const float*)d_in[12];
    const float* ln2_b  = (const float*)d_in[13];
    const float* w1     = (const float*)d_in[14];
    const float* b1     = (const float*)d_in[15];
    const float* w2     = (const float*)d_in[16];
    const float* b2     = (const float*)d_in[17];
    float* out = (float*)d_out;

    float *p_xw, *p_qkv, *p_att, *p_hs, *p_y, *p_mid, *p_wqkv, *p_bqkv;
    cudaGetSymbolAddress((void**)&p_xw,   g_xw);
    cudaGetSymbolAddress((void**)&p_qkv,  g_qkv);
    cudaGetSymbolAddress((void**)&p_att,  g_att);
    cudaGetSymbolAddress((void**)&p_hs,   g_hs);
    cudaGetSymbolAddress((void**)&p_y,    g_y);
    cudaGetSymbolAddress((void**)&p_mid,  g_mid);
    cudaGetSymbolAddress((void**)&p_wqkv, g_wqkv);
    cudaGetSymbolAddress((void**)&p_bqkv, g_bqkv);

    cudaFuncSetAttribute(tf32gemm<2>,   cudaFuncAttributeMaxDynamicSharedMemorySize, SMEM_SZ);
    cudaFuncSetAttribute(tf32gemm_s<0>, cudaFuncAttributeMaxDynamicSharedMemorySize, SMEM_S);
    cudaFuncSetAttribute(tf32gemm_s<1>, cudaFuncAttributeMaxDynamicSharedMemorySize, SMEM_S);
    cudaFuncSetAttribute(tf32gemm_s<3>, cudaFuncAttributeMaxDynamicSharedMemorySize, SMEM_S);

    dim3 blk(256);

    pack_qkv<<<768, blk>>>(wq, wk, wv, bq, bk, bv, p_wqkv, p_bqkv);
    ln_kernel<<<M_TOK / 8, blk>>>(hidden, ln1_g, ln1_b, p_xw, 1);
    tf32gemm_s<0><<<dim3(768 / SBN, M_TOK / BM), blk, SMEM_S>>>(
        p_xw, p_wqkv, p_bqkv, nullptr, p_qkv, M_TOK, 768, C_DIM);
    attn_kernel<<<dim3(2048, 8), dim3(128)>>>(p_qkv, bt, p_att);
    // wo-projection + scatter + residual -> hs, fused LN2 -> y (big tile)
    tf32gemm<2><<<dim3(C_DIM / BN, M_TOK / BM), blk, SMEM_SZ>>>(
        p_att, wo, bo, hidden, p_hs, M_TOK, C_DIM, C_DIM,
        ln2_g, ln2_b, p_y);
    tf32gemm_s<1><<<dim3(DFF / SBN, M_TOK / BM), blk, SMEM_S>>>(
        p_y, w1, b1, nullptr, p_mid, M_TOK, DFF, C_DIM);
    tf32gemm_s<3><<<dim3(C_DIM / SBN, M_TOK / BM), blk, SMEM_S>>>(
        p_mid, w2, b2, p_hs, out, M_TOK, C_DIM, DFF);
}

// round 16
// speedup vs baseline: 1.1952x; 1.0074x over previous
#include <cuda_runtime.h>
#include <math.h>
#include <stdint.h>

// ---------------------------------------------------------------------------
// Problem constants: B=32, H=W=64, C=256, NH=8, hd=32, WS=8, SS=4, IM=4
// ---------------------------------------------------------------------------
#define M_TOK   131072
#define C_DIM   256
#define DFF     1024

// Scratch (device globals; no allocation at runtime)
__device__ float g_xw   [M_TOK * C_DIM];
__device__ float g_qkv  [M_TOK * 768];
__device__ float g_att  [M_TOK * C_DIM];
__device__ float g_hs   [M_TOK * C_DIM];
__device__ float g_y    [M_TOK * C_DIM];
__device__ float g_mid  [M_TOK * DFF];
__device__ float g_wqkv [C_DIM * 768];
__device__ float g_bqkv [768];

// ---------------------------------------------------------------------------
// cp.async helpers
// ---------------------------------------------------------------------------
__device__ __forceinline__ void cp_async16(void* smem, const void* gmem) {
    uint32_t s = (uint32_t)__cvta_generic_to_shared(smem);
    asm volatile("cp.async.cg.shared.global [%0], [%1], 16;\n" :: "r"(s), "l"(gmem));
}
__device__ __forceinline__ void cp_commit() {
    asm volatile("cp.async.commit_group;\n");
}
template<int N>
__device__ __forceinline__ void cp_wait() {
    asm volatile("cp.async.wait_group %0;\n" :: "n"(N));
}

__device__ __forceinline__ void mma_tf32(float d[4], const uint32_t a[4], const uint32_t b[2]) {
    asm volatile(
        "mma.sync.aligned.m16n8k8.row.col.f32.tf32.tf32.f32 "
        "{%0,%1,%2,%3}, {%4,%5,%6,%7}, {%8,%9}, {%0,%1,%2,%3};\n"
        : "+f"(d[0]), "+f"(d[1]), "+f"(d[2]), "+f"(d[3])
        : "r"(a[0]), "r"(a[1]), "r"(a[2]), "r"(a[3]), "r"(b[0]), "r"(b[1]));
}

// ---------------------------------------------------------------------------
// Pack wq|wk|wv -> [256,768], bq|bk|bv -> [768]
// ---------------------------------------------------------------------------
__global__ __launch_bounds__(256) void pack_qkv(
    const float* __restrict__ wq, const float* __restrict__ wk,
    const float* __restrict__ wv, const float* __restrict__ bq,
    const float* __restrict__ bk, const float* __restrict__ bv,
    float* __restrict__ wdst, float* __restrict__ bdst)
{
    int idx = blockIdx.x * 256 + threadIdx.x;
    int k = idx / 768, n = idx % 768;
    float v = (n < 256) ? wq[k * 256 + n]
            : (n < 512) ? wk[k * 256 + n - 256]
                        : wv[k * 256 + n - 512];
    wdst[idx] = v;
    if (idx < 768)
        bdst[idx] = (idx < 256) ? bq[idx] : (idx < 512) ? bk[idx - 256] : bv[idx - 512];
}

// ---------------------------------------------------------------------------
// LayerNorm: warp-per-token, 8 tokens/block, float4 I/O. (LN1 only)
// ---------------------------------------------------------------------------
__global__ __launch_bounds__(256) void ln_kernel(
    const float* __restrict__ x, const float* __restrict__ g,
    const float* __restrict__ bb, float* __restrict__ out, int gather)
{
    int warp = threadIdx.x >> 5, lane = threadIdx.x & 31;
    int r = blockIdx.x * 8 + warp;
    long src;
    if (gather) {
        int b  = r >> 12;
        int wi = (r >> 9) & 7, wj = (r >> 6) & 7;
        int pi = (r >> 3) & 7, pj = r & 7;
        int h = (wi * 8 + pi + 4) & 63;
        int w = (wj * 8 + pj + 4) & 63;
        src = (long)b * 4096 + h * 64 + w;
    } else {
        src = r;
    }
    const float4* xp = (const float4*)(x + src * C_DIM);
    float4 v0 = xp[lane * 2], v1 = xp[lane * 2 + 1];
    float s  = v0.x + v0.y + v0.z + v0.w + v1.x + v1.y + v1.z + v1.w;
    float s2 = v0.x*v0.x + v0.y*v0.y + v0.z*v0.z + v0.w*v0.w
             + v1.x*v1.x + v1.y*v1.y + v1.z*v1.z + v1.w*v1.w;
    #pragma unroll
    for (int o = 16; o > 0; o >>= 1) {
        s  += __shfl_xor_sync(0xffffffffu, s, o);
        s2 += __shfl_xor_sync(0xffffffffu, s2, o);
    }
    float mean = s * (1.f / 256.f);
    float var  = s2 * (1.f / 256.f) - mean * mean;
    float rstd = rsqrtf(var + 1e-5f);
    const float4* gp = (const float4*)(g  + lane * 8);
    const float4* bp = (const float4*)(bb + lane * 8);
    float4 g0 = gp[0], g1 = gp[1], b0 = bp[0], b1 = bp[1];
    float4 o0, o1;
    o0.x = (v0.x - mean) * rstd * g0.x + b0.x;
    o0.y = (v0.y - mean) * rstd * g0.y + b0.y;
    o0.z = (v0.z - mean) * rstd * g0.z + b0.z;
    o0.w = (v0.w - mean) * rstd * g0.w + b0.w;
    o1.x = (v1.x - mean) * rstd * g1.x + b1.x;
    o1.y = (v1.y - mean) * rstd * g1.y + b1.y;
    o1.z = (v1.z - mean) * rstd * g1.z + b1.z;
    o1.w = (v1.w - mean) * rstd * g1.w + b1.w;
    float4* op = (float4*)(out + (long)r * C_DIM + lane * 8);
    op[0] = o0; op[1] = o1;
}

// ===========================================================================
// BIG-TILE GEMM (128x256, 1 CTA/SM) — EPI==2 only: wo + scatter + residual
// -> hs, fused LN2 -> Y. (Proven R12 kernel.)
// ===========================================================================
#define NSTG 3
#define BM   128
#define BN   256
#define BK   32
#define ASTR 36
#define BSTR 264
#define A_STAGE (BM * ASTR)
#define B_STAGE (BK * BSTR)
#define SMEM_SZ ((NSTG * (A_STAGE + B_STAGE)) * 4)

template<int EPI>
__global__ __launch_bounds__(256, 1) void tf32gemm(
    const float* __restrict__ A, const float* __restrict__ B,
    const float* __restrict__ bias, const float* __restrict__ R,
    float* __restrict__ C, int M, int N, int K,
    const float* __restrict__ G2, const float* __restrict__ B2,
    float* __restrict__ Y)
{
    extern __shared__ float sm[];
    float* Asm = sm;
    float* Bsm = sm + NSTG * A_STAGE;

    int tid  = threadIdx.x;
    int lane = tid & 31, warp = tid >> 5;
    int wm = warp >> 2, wn = warp & 3;
    int bm = blockIdx.y * BM, bn = blockIdx.x * BN;
    int gid = lane >> 2, tig = lane & 3;

    float acc[4][8][4];
    #pragma unroll
    for (int mt = 0; mt < 4; mt++)
        #pragma unroll
        for (int nt = 0; nt < 8; nt++)
            #pragma unroll
            for (int i = 0; i < 4; i++) acc[mt][nt][i] = 0.f;

    int aR[4], aC[4], bR[8], bC[8];
    #pragma unroll
    for (int i = 0; i < 4; i++) {
        int s = tid + i * 256;
        aR[i] = s >> 3;  aC[i] = (s & 7) * 4;
    }
    #pragma unroll
    for (int i = 0; i < 8; i++) {
        int s = tid + i * 256;
        bR[i] = s >> 6;  bC[i] = (s & 63) * 4;
    }

    int KT = K >> 5;

    #pragma unroll
    for (int s = 0; s < NSTG - 1; s++) {
        int kb = s << 5;
        float* as = Asm + s * A_STAGE;
        float* bs = Bsm + s * B_STAGE;
        #pragma unroll
        for (int i = 0; i < 4; i++)
            cp_async16(&as[aR[i] * ASTR + aC[i]], A + (long)(bm + aR[i]) * K + kb + aC[i]);
        #pragma unroll
        for (int i = 0; i < 8; i++)
            cp_async16(&bs[bR[i] * BSTR + bC[i]], B + (long)(kb + bR[i]) * N + bn + bC[i]);
        cp_commit();
    }

    for (int kt = 0; kt < KT; kt++) {
        if (kt + NSTG - 1 < KT) cp_wait<NSTG - 2>(); else cp_wait<0>();
        __syncthreads();
        int stg = kt % NSTG;
        const float* as = Asm + stg * A_STAGE;
        const float* bs = Bsm + stg * B_STAGE;
        #pragma unroll
        for (int ks = 0; ks < 4; ks++) {
            uint32_t af[4][4], bf[8][2];
            #pragma unroll
            for (int mt = 0; mt < 4; mt++) {
                int r0 = wm * 64 + mt * 16 + gid;
                int c0 = ks * 8 + tig;
                af[mt][0] = __float_as_uint(as[r0 * ASTR + c0]);
                af[mt][1] = __float_as_uint(as[(r0 + 8) * ASTR + c0]);
                af[mt][2] = __float_as_uint(as[r0 * ASTR + c0 + 4]);
                af[mt][3] = __float_as_uint(as[(r0 + 8) * ASTR + c0 + 4]);
            }
            #pragma unroll
            for (int nt = 0; nt < 8; nt++) {
                int rr = ks * 8 + tig;
                int cc = wn * 64 + nt * 8 + gid;
                bf[nt][0] = __float_as_uint(bs[rr * BSTR + cc]);
                bf[nt][1] = __float_as_uint(bs[(rr + 4) * BSTR + cc]);
            }
            #pragma unroll
            for (int mt = 0; mt < 4; mt++)
                #pragma unroll
                for (int nt = 0; nt < 8; nt++)
                    mma_tf32(acc[mt][nt], af[mt], bf[nt]);
        }
        if (kt + NSTG - 1 < KT) {
            int kn = kt + NSTG - 1;
            int kb = kn << 5;
            int ds = kn % NSTG;
            float* asn = Asm + ds * A_STAGE;
            float* bsn = Bsm + ds * B_STAGE;
            #pragma unroll
            for (int i = 0; i < 4; i++)
                cp_async16(&asn[aR[i] * ASTR + aC[i]], A + (long)(bm + aR[i]) * K + kb + aC[i]);
            #pragma unroll
            for (int i = 0; i < 8; i++)
                cp_async16(&bsn[bR[i] * BSTR + bC[i]], B + (long)(kb + bR[i]) * N + bn + bC[i]);
            cp_commit();
        }
    }

    if (EPI == 2) {
        __syncthreads();
        float* red = sm;
        long orows[4][2];
        float rsum[4][2], rsq[4][2];
        #pragma unroll
        for (int mt = 0; mt < 4; mt++) {
            #pragma unroll
            for (int half = 0; half < 2; half++) {
                int row = bm + wm * 64 + mt * 16 + half * 8 + gid;
                int b  = row >> 12;
                int wi = (row >> 9) & 7, wj = (row >> 6) & 7;
                int pi = (row >> 3) & 7, pj = row & 7;
                int h = (wi * 8 + pi + 4) & 63;
                int w = (wj * 8 + pj + 4) & 63;
                long orow = (long)b * 4096 + h * 64 + w;
                orows[mt][half] = orow;
                float s = 0.f, q = 0.f;
                #pragma unroll
                for (int nt = 0; nt < 8; nt++) {
                    int col = bn + wn * 64 + nt * 8 + 2 * tig;
                    float v0 = acc[mt][nt][half * 2 + 0] + bias[col];
                    float v1 = acc[mt][nt][half * 2 + 1] + bias[col + 1];
                    float2 rr = *(const float2*)(R + orow * N + col);
                    v0 += rr.x; v1 += rr.y;
                    acc[mt][nt][half * 2 + 0] = v0;
                    acc[mt][nt][half * 2 + 1] = v1;
                    s += v0 + v1;
                    q += v0 * v0 + v1 * v1;
                    float2 o; o.x = v0; o.y = v1;
                    *(float2*)(C + orow * N + col) = o;
                }
                rsum[mt][half] = s; rsq[mt][half] = q;
            }
        }
        #pragma unroll
        for (int mt = 0; mt < 4; mt++) {
            #pragma unroll
            for (int half = 0; half < 2; half++) {
                float s = rsum[mt][half], q = rsq[mt][half];
                s += __shfl_xor_sync(0xffffffffu, s, 1);
                q += __shfl_xor_sync(0xffffffffu, q, 1);
                s += __shfl_xor_sync(0xffffffffu, s, 2);
                q += __shfl_xor_sync(0xffffffffu, q, 2);
                if (tig == 0) {
                    int lr = wm * 64 + mt * 16 + half * 8 + gid;
                    red[lr * 8 + wn * 2]     = s;
                    red[lr * 8 + wn * 2 + 1] = q;
                }
            }
        }
        __syncthreads();
        #pragma unroll
        for (int mt = 0; mt < 4; mt++) {
            #pragma unroll
            for (int half = 0; half < 2; half++) {
                int lr = wm * 64 + mt * 16 + half * 8 + gid;
                float s = red[lr*8+0] + red[lr*8+2] + red[lr*8+4] + red[lr*8+6];
                float q = red[lr*8+1] + red[lr*8+3] + red[lr*8+5] + red[lr*8+7];
                float mean = s * (1.f / 256.f);
                float var  = q * (1.f / 256.f) - mean * mean;
                float rstd = rsqrtf(var + 1e-5f);
                long orow = orows[mt][half];
                #pragma unroll
                for (int nt = 0; nt < 8; nt++) {
                    int col = bn + wn * 64 + nt * 8 + 2 * tig;
                    float v0 = acc[mt][nt][half * 2 + 0];
                    float v1 = acc[mt][nt][half * 2 + 1];
                    float2 o;
                    o.x = (v0 - mean) * rstd * G2[col]     + B2[col];
                    o.y = (v1 - mean) * rstd * G2[col + 1] + B2[col + 1];
                    *(float2*)(Y + orow * N + col) = o;
                }
            }
        }
        return;
    }
}

// ===========================================================================
// SMALL-TILE GEMM (128x128, 2 CTAs/SM) — EPI 0 plain, 1 GELU, 3 residual.
// ===========================================================================
#define SBN     128
#define SBSTR   136
#define SB_STAGE (BK * SBSTR)
#define SMEM_S  ((NSTG * (A_STAGE + SB_STAGE)) * 4)

template<int EPI>
__global__ __launch_bounds__(256, 2) void tf32gemm_s(
    const float* __restrict__ A, const float* __restrict__ B,
    const float* __restrict__ bias, const float* __restrict__ R,
    float* __restrict__ C, int M, int N, int K)
{
    extern __shared__ float sm[];
    float* Asm = sm;
    float* Bsm = sm + NSTG * A_STAGE;

    int tid  = threadIdx.x;
    int lane = tid & 31, warp = tid >> 5;
    int wm = warp >> 2, wn = warp & 3;
    int bm = blockIdx.y * BM, bn = blockIdx.x * SBN;
    int gid = lane >> 2, tig = lane & 3;

    float acc[4][4][4];
    #pragma unroll
    for (int mt = 0; mt < 4; mt++)
        #pragma unroll
        for (int nt = 0; nt < 4; nt++)
            #pragma unroll
            for (int i = 0; i < 4; i++) acc[mt][nt][i] = 0.f;

    int aR[4], aC[4], bR[4], bC[4];
    #pragma unroll
    for (int i = 0; i < 4; i++) {
        int s = tid + i * 256;
        aR[i] = s >> 3;  aC[i] = (s & 7) * 4;
        bR[i] = s >> 5;  bC[i] = (s & 31) * 4;
    }

    int KT = K >> 5;

    #pragma unroll
    for (int s = 0; s < NSTG - 1; s++) {
        int kb = s << 5;
        float* as = Asm + s * A_STAGE;
        float* bs = Bsm + s * SB_STAGE;
        #pragma unroll
        for (int i = 0; i < 4; i++) {
            cp_async16(&as[aR[i] * ASTR + aC[i]], A + (long)(bm + aR[i]) * K + kb + aC[i]);
            cp_async16(&bs[bR[i] * SBSTR + bC[i]], B + (long)(kb + bR[i]) * N + bn + bC[i]);
        }
        cp_commit();
    }

    for (int kt = 0; kt < KT; kt++) {
        if (kt + NSTG - 1 < KT) cp_wait<NSTG - 2>(); else cp_wait<0>();
        __syncthreads();
        int stg = kt % NSTG;
        const float* as = Asm + stg * A_STAGE;
        const float* bs = Bsm + stg * SB_STAGE;
        #pragma unroll
        for (int ks = 0; ks < 4; ks++) {
            uint32_t af[4][4], bf[4][2];
            #pragma unroll
            for (int mt = 0; mt < 4; mt++) {
                int r0 = wm * 64 + mt * 16 + gid;
                int c0 = ks * 8 + tig;
                af[mt][0] = __float_as_uint(as[r0 * ASTR + c0]);
                af[mt][1] = __float_as_uint(as[(r0 + 8) * ASTR + c0]);
                af[mt][2] = __float_as_uint(as[r0 * ASTR + c0 + 4]);
                af[mt][3] = __float_as_uint(as[(r0 + 8) * ASTR + c0 + 4]);
            }
            #pragma unroll
            for (int nt = 0; nt < 4; nt++) {
                int rr = ks * 8 + tig;
                int cc = wn * 32 + nt * 8 + gid;
                bf[nt][0] = __float_as_uint(bs[rr * SBSTR + cc]);
                bf[nt][1] = __float_as_uint(bs[(rr + 4) * SBSTR + cc]);
            }
            #pragma unroll
            for (int mt = 0; mt < 4; mt++)
                #pragma unroll
                for (int nt = 0; nt < 4; nt++)
                    mma_tf32(acc[mt][nt], af[mt], bf[nt]);
        }
        if (kt + NSTG - 1 < KT) {
            int kn = kt + NSTG - 1;
            int kb = kn << 5;
            int ds = kn % NSTG;
            float* asn = Asm + ds * A_STAGE;
            float* bsn = Bsm + ds * SB_STAGE;
            #pragma unroll
            for (int i = 0; i < 4; i++) {
                cp_async16(&asn[aR[i] * ASTR + aC[i]], A + (long)(bm + aR[i]) * K + kb + aC[i]);
                cp_async16(&bsn[bR[i] * SBSTR + bC[i]], B + (long)(kb + bR[i]) * N + bn + bC[i]);
            }
            cp_commit();
        }
    }

    #pragma unroll
    for (int mt = 0; mt < 4; mt++) {
        #pragma unroll
        for (int half = 0; half < 2; half++) {
            int row = bm + wm * 64 + mt * 16 + half * 8 + gid;
            #pragma unroll
            for (int nt = 0; nt < 4; nt++) {
                int col = bn + wn * 32 + nt * 8 + 2 * tig;
                float v0 = acc[mt][nt][half * 2 + 0] + bias[col];
                float v1 = acc[mt][nt][half * 2 + 1] + bias[col + 1];
                if (EPI == 1) {
                    v0 = 0.5f * v0 * (1.f + erff(v0 * 0.70710678118654752f));
                    v1 = 0.5f * v1 * (1.f + erff(v1 * 0.70710678118654752f));
                }
                if (EPI == 3) {
                    float2 rr = *(const float2*)(R + (long)row * N + col);
                    v0 += rr.x; v1 += rr.y;
                }
                float2 o; o.x = v0; o.y = v1;
                *(float2*)(C + (long)row * N + col) = o;
            }
        }
    }
}

// ---------------------------------------------------------------------------
// Tensor-core windowed attention, 1xTF32.
// R16: P-matrix smem ALIASES Q/K smem (dead after QK MMAs; barrier added),
// dropping smem ~47KB -> ~30KB; __launch_bounds__(128,6) -> occ 24% -> 37%.
// ---------------------------------------------------------------------------
#define QSTR 36
#define VSTR 40
#define PSTR 68

__device__ __forceinline__ int bandf(int z) { return z < 56 ? 0 : (z < 60 ? 1 : 2); }

__global__ __launch_bounds__(128, 6) void attn_kernel(
    const float* __restrict__ QKV, const float* __restrict__ bt,
    float* __restrict__ O)
{
    __shared__ float QKs[64 * QSTR * 2];     // Qs | Ks; later reused as Ps
    __shared__ float Vs[64 * VSTR];
    __shared__ float btS[228];
    float* Qs = QKs;
    float* Ks = QKs + 64 * QSTR;
    float* Ps = QKs;                         // alias (64*68 <= 64*72)

    int win  = blockIdx.x;
    int head = blockIdx.y;
    int t = threadIdx.x;
    int warp = t >> 5, lane = t & 31;
    int gid = lane >> 2, tig = lane & 3;
    long base = (long)win * 64 * 768 + head * 32;

    for (int i = t; i < 225; i += 128) btS[i] = bt[i * 8 + head];

    const float scale = 0.17677669529663687f;
    #pragma unroll
    for (int i = 0; i < 4; i++) {
        int idx = t + i * 128;
        int row = idx >> 3, c4 = (idx & 7) * 4;
        const float* src = QKV + base + (long)row * 768 + c4;
        float4 q = *(const float4*)(src);
        q.x *= scale; q.y *= scale; q.z *= scale; q.w *= scale;
        *(float4*)&Qs[row * QSTR + c4] = q;
        *(float4*)&Ks[row * QSTR + c4] = *(const float4*)(src + 256);
        *(float4*)&Vs[row * VSTR + c4] = *(const float4*)(src + 512);
    }
    __syncthreads();

    // ---- S = Q@K^T : warp covers key-cols [warp*16, warp*16+16) ----
    float sc[4][2][4];
    #pragma unroll
    for (int mt = 0; mt < 4; mt++)
        #pragma unroll
        for (int nt = 0; nt < 2; nt++)
            #pragma unroll
            for (int i = 0; i < 4; i++) sc[mt][nt][i] = 0.f;

    #pragma unroll
    for (int kt = 0; kt < 4; kt++) {
        uint32_t af[4][4], bf[2][2];
        #pragma unroll
        for (int mt = 0; mt < 4; mt++) {
            int r0 = mt * 16 + gid;
            int c0 = kt * 8 + tig;
            af[mt][0] = __float_as_uint(Qs[r0 * QSTR + c0]);
            af[mt][1] = __float_as_uint(Qs[(r0 + 8) * QSTR + c0]);
            af[mt][2] = __float_as_uint(Qs[r0 * QSTR + c0 + 4]);
            af[mt][3] = __float_as_uint(Qs[(r0 + 8) * QSTR + c0 + 4]);
        }
        #pragma unroll
        for (int nt = 0; nt < 2; nt++) {
            int kr = warp * 16 + nt * 8 + gid;
            int kc = kt * 8 + tig;
            bf[nt][0] = __float_as_uint(Ks[kr * QSTR + kc]);
            bf[nt][1] = __float_as_uint(Ks[kr * QSTR + kc + 4]);
        }
        #pragma unroll
        for (int mt = 0; mt < 4; mt++)
            #pragma unroll
            for (int nt = 0; nt < 2; nt++)
                mma_tf32(sc[mt][nt], af[mt], bf[nt]);
    }
    __syncthreads();   // Q/K reads complete before Ps overwrites the aliased smem

    // ---- bias + shift mask, store S to Ps ----
    int w_in_b = win & 63;
    int wwi = w_in_b >> 3, wwj = w_in_b & 7;
    bool edge = (wwi == 7) || (wwj == 7);
    #pragma unroll
    for (int mt = 0; mt < 4; mt++) {
        #pragma unroll
        for (int half = 0; half < 2; half++) {
            int r = mt * 16 + half * 8 + gid;
            int yi = r >> 3, xi = r & 7;
            int id_i = edge ? bandf(wwi * 8 + yi) * 3 + bandf(wwj * 8 + xi) : 0;
            #pragma unroll
            for (int nt = 0; nt < 2; nt++) {
                int c0 = warp * 16 + nt * 8 + 2 * tig;
                float v0 = sc[mt][nt][half * 2 + 0];
                float v1 = sc[mt][nt][half * 2 + 1];
                #pragma unroll
                for (int j = 0; j < 2; j++) {
                    int c = c0 + j;
                    int yj = c >> 3, xj = c & 7;
                    float add = btS[(yi - yj + 7) * 15 + (xi - xj + 7)];
                    if (edge) {
                        int id_j = bandf(wwi * 8 + yj) * 3 + bandf(wwj * 8 + xj);
                        if (id_i != id_j) add -= 100.f;
                    }
                    if (j == 0) v0 += add; else v1 += add;
                }
                float2 st; st.x = v0; st.y = v1;
                *(float2*)&Ps[r * PSTR + c0] = st;
            }
        }
    }
    __syncthreads();

    // ---- softmax: thread handles half a row ----
    {
        int row = t >> 1;
        int c0 = (t & 1) * 32;
        float4 e[8];
        float mx = -1e30f;
        #pragma unroll
        for (int i = 0; i < 8; i++) {
            e[i] = *(const float4*)&Ps[row * PSTR + c0 + i * 4];
            mx = fmaxf(mx, fmaxf(fmaxf(e[i].x, e[i].y), fmaxf(e[i].z, e[i].w)));
        }
        mx = fmaxf(mx, __shfl_xor_sync(0xffffffffu, mx, 1));
        float sum = 0.f;
        #pragma unroll
        for (int i = 0; i < 8; i++) {
            e[i].x = __expf(e[i].x - mx); e[i].y = __expf(e[i].y - mx);
            e[i].z = __expf(e[i].z - mx); e[i].w = __expf(e[i].w - mx);
            sum += e[i].x + e[i].y + e[i].z + e[i].w;
        }
        sum += __shfl_xor_sync(0xffffffffu, sum, 1);
        float rs = 1.f / sum;
        #pragma unroll
        for (int i = 0; i < 8; i++) {
            e[i].x *= rs; e[i].y *= rs; e[i].z *= rs; e[i].w *= rs;
            *(float4*)&Ps[row * PSTR + c0 + i * 4] = e[i];
        }
    }
    __syncthreads();

    // ---- O = P@V : warp covers query-rows [warp*16, warp*16+16) ----
    float oc[4][4];
    #pragma unroll
    for (int nt = 0; nt < 4; nt++)
        #pragma unroll
        for (int i = 0; i < 4; i++) oc[nt][i] = 0.f;

    #pragma unroll
    for (int kt = 0; kt < 8; kt++) {
        uint32_t af[4], bf[4][2];
        int r0 = warp * 16 + gid;
        int c0 = kt * 8 + tig;
        af[0] = __float_as_uint(Ps[r0 * PSTR + c0]);
        af[1] = __float_as_uint(Ps[(r0 + 8) * PSTR + c0]);
        af[2] = __float_as_uint(Ps[r0 * PSTR + c0 + 4]);
        af[3] = __float_as_uint(Ps[(r0 + 8) * PSTR + c0 + 4]);
        #pragma unroll
        for (int nt = 0; nt < 4; nt++) {
            int vr = kt * 8 + tig;
            int vc = nt * 8 + gid;
            bf[nt][0] = __float_as_uint(Vs[vr * VSTR + vc]);
            bf[nt][1] = __float_as_uint(Vs[(vr + 4) * VSTR + vc]);
        }
        #pragma unroll
        for (int nt = 0; nt < 4; nt++)
            mma_tf32(oc[nt], af, bf[nt]);
    }

    long obase = ((long)win * 64) * C_DIM + head * 32;
    #pragma unroll
    for (int half = 0; half < 2; half++) {
        int row = warp * 16 + half * 8 + gid;
        #pragma unroll
        for (int nt = 0; nt < 4; nt++) {
            int col = nt * 8 + 2 * tig;
            float2 o;
            o.x = oc[nt][half * 2 + 0];
            o.y = oc[nt][half * 2 + 1];
            *(float2*)(O + obase + (long)row * C_DIM + col) = o;
        }
    }
}

// ---------------------------------------------------------------------------
// Launch
// ---------------------------------------------------------------------------
extern "C" void kernel_launch(void* const* d_in, const int* in_sizes, int n_in,
                              void* d_out, int out_size)
{
    const float* hidden = (const float*)d_in[0];
    const float* ln1_g  = (const float*)d_in[1];
    const float* ln1_b  = (const float*)d_in[2];
    const float* wq     = (const float*)d_in[3];
    const float* bq     = (const float*)d_in[4];
    const float* wk     = (const float*)d_in[5];
    const float* bk     = (const float*)d_in[6];
    const float* wv     = (const float*)d_in[7];
    const float* bv     = (const float*)d_in[8];
    const float* bt     = (const float*)d_in[9];
    const float* wo     = (const float*)d_in[10];
    const float* bo     = (const float*)d_in[11];
    const float* ln2_g  = (const float*)d_in[12];
    const float* ln2_b  = (const float*)d_in[13];
    const float* w1     = (const float*)d_in[14];
    const float* b1     = (const float*)d_in[15];
    const float* w2     = (const float*)d_in[16];
    const float* b2     = (const float*)d_in[17];
    float* out = (float*)d_out;

    float *p_xw, *p_qkv, *p_att, *p_hs, *p_y, *p_mid, *p_wqkv, *p_bqkv;
    cudaGetSymbolAddress((void**)&p_xw,   g_xw);
    cudaGetSymbolAddress((void**)&p_qkv,  g_qkv);
    cudaGetSymbolAddress((void**)&p_att,  g_att);
    cudaGetSymbolAddress((void**)&p_hs,   g_hs);
    cudaGetSymbolAddress((void**)&p_y,    g_y);
    cudaGetSymbolAddress((void**)&p_mid,  g_mid);
    cudaGetSymbolAddress((void**)&p_wqkv, g_wqkv);
    cudaGetSymbolAddress((void**)&p_bqkv, g_bqkv);

    cudaFuncSetAttribute(tf32gemm<2>,   cudaFuncAttributeMaxDynamicSharedMemorySize, SMEM_SZ);
    cudaFuncSetAttribute(tf32gemm_s<0>, cudaFuncAttributeMaxDynamicSharedMemorySize, SMEM_S);
    cudaFuncSetAttribute(tf32gemm_s<1>, cudaFuncAttributeMaxDynamicSharedMemorySize, SMEM_S);
    cudaFuncSetAttribute(tf32gemm_s<3>, cudaFuncAttributeMaxDynamicSharedMemorySize, SMEM_S);

    dim3 blk(256);

    pack_qkv<<<768, blk>>>(wq, wk, wv, bq, bk, bv, p_wqkv, p_bqkv);
    ln_kernel<<<M_TOK / 8, blk>>>(hidden, ln1_g, ln1_b, p_xw, 1);
    tf32gemm_s<0><<<dim3(768 / SBN, M_TOK / BM), blk, SMEM_S>>>(
        p_xw, p_wqkv, p_bqkv, nullptr, p_qkv, M_TOK, 768, C_DIM);
    attn_kernel<<<dim3(2048, 8), dim3(128)>>>(p_qkv, bt, p_att);
    tf32gemm<2><<<dim3(C_DIM / BN, M_TOK / BM), blk, SMEM_SZ>>>(
        p_att, wo, bo, hidden, p_hs, M_TOK, C_DIM, C_DIM,
        ln2_g, ln2_b, p_y);
    tf32gemm_s<1><<<dim3(DFF / SBN, M_TOK / BM), blk, SMEM_S>>>(
        p_y, w1, b1, nullptr, p_mid, M_TOK, DFF, C_DIM);
    tf32gemm_s<3><<<dim3(C_DIM / SBN, M_TOK / BM), blk, SMEM_S>>>(
        p_mid, w2, b2, p_hs, out, M_TOK, C_DIM, DFF);
}

// round 17
// speedup vs baseline: 1.5695x; 1.3131x over previous
#include <cuda_runtime.h>
#include <cuda_fp16.h>
#include <math.h>
#include <stdint.h>

// ---------------------------------------------------------------------------
// Problem constants: B=32, H=W=64, C=256, NH=8, hd=32, WS=8, SS=4, IM=4
// ---------------------------------------------------------------------------
#define M_TOK   131072
#define C_DIM   256
#define DFF     1024

// Scratch (device globals)
__device__ __half g_xw_h  [M_TOK * C_DIM];
__device__ float  g_qkv   [M_TOK * 768];
__device__ __half g_att_h [M_TOK * C_DIM];
__device__ float  g_hs    [M_TOK * C_DIM];
__device__ __half g_y_h   [M_TOK * C_DIM];
__device__ __half g_mid_h [M_TOK * DFF];
__device__ __half g_wqkvT [768 * C_DIM];     // [N][K] half
__device__ float  g_bqkv  [768];
__device__ __half g_w1T   [DFF * C_DIM];     // [1024][256]
__device__ __half g_w2T   [C_DIM * DFF];     // [256][1024]
__device__ __half g_woT   [C_DIM * C_DIM];   // [256][256]

// ---------------------------------------------------------------------------
// helpers
// ---------------------------------------------------------------------------
__device__ __forceinline__ void cp_async16(void* smem, const void* gmem) {
    uint32_t s = (uint32_t)__cvta_generic_to_shared(smem);
    asm volatile("cp.async.cg.shared.global [%0], [%1], 16;\n" :: "r"(s), "l"(gmem));
}
__device__ __forceinline__ void cp_commit() {
    asm volatile("cp.async.commit_group;\n");
}
template<int N>
__device__ __forceinline__ void cp_wait() {
    asm volatile("cp.async.wait_group %0;\n" :: "n"(N));
}
__device__ __forceinline__ void mma_tf32(float d[4], const uint32_t a[4], const uint32_t b[2]) {
    asm volatile(
        "mma.sync.aligned.m16n8k8.row.col.f32.tf32.tf32.f32 "
        "{%0,%1,%2,%3}, {%4,%5,%6,%7}, {%8,%9}, {%0,%1,%2,%3};\n"
        : "+f"(d[0]), "+f"(d[1]), "+f"(d[2]), "+f"(d[3])
        : "r"(a[0]), "r"(a[1]), "r"(a[2]), "r"(a[3]), "r"(b[0]), "r"(b[1]));
}
__device__ __forceinline__ void mma_f16(float d[4], const uint32_t a[4], const uint32_t b[2]) {
    asm volatile(
        "mma.sync.aligned.m16n8k16.row.col.f32.f16.f16.f32 "
        "{%0,%1,%2,%3}, {%4,%5,%6,%7}, {%8,%9}, {%0,%1,%2,%3};\n"
        : "+f"(d[0]), "+f"(d[1]), "+f"(d[2]), "+f"(d[3])
        : "r"(a[0]), "r"(a[1]), "r"(a[2]), "r"(a[3]), "r"(b[0]), "r"(b[1]));
}

// ---------------------------------------------------------------------------
// Weight transpose+convert kernels (one-time, tiny)
// ---------------------------------------------------------------------------
__global__ __launch_bounds__(256) void pack_qkvT(
    const float* __restrict__ wq, const float* __restrict__ wk,
    const float* __restrict__ wv, const float* __restrict__ bq,
    const float* __restrict__ bk, const float* __restrict__ bv,
    __half* __restrict__ wT, float* __restrict__ bdst)
{
    int idx = blockIdx.x * 256 + threadIdx.x;    // 0 .. 196607
    int n = idx >> 8, k = idx & 255;
    const float* src = (n < 256) ? wq : (n < 512) ? wk : wv;
    wT[idx] = __float2half(src[k * 256 + (n & 255)]);
    if (idx < 768)
        bdst[idx] = (idx < 256) ? bq[idx] : (idx < 512) ? bk[idx - 256] : bv[idx - 512];
}
__global__ __launch_bounds__(256) void transpose_w1(
    const float* __restrict__ w1, __half* __restrict__ wT)
{
    int idx = blockIdx.x * 256 + threadIdx.x;
    int n = idx >> 8, k = idx & 255;             // n<1024, k<256
    wT[idx] = __float2half(w1[k * DFF + n]);
}
__global__ __launch_bounds__(256) void transpose_w2(
    const float* __restrict__ w2, __half* __restrict__ wT)
{
    int idx = blockIdx.x * 256 + threadIdx.x;
    int n = idx / DFF, k = idx % DFF;            // n<256, k<1024
    wT[idx] = __float2half(w2[k * C_DIM + n]);
}
__global__ __launch_bounds__(256) void transpose_wo(
    const float* __restrict__ wo, __half* __restrict__ wT)
{
    int idx = blockIdx.x * 256 + threadIdx.x;    // 0..65535
    int n = idx >> 8, k = idx & 255;
    wT[idx] = __float2half(wo[k * C_DIM + n]);
}

// ---------------------------------------------------------------------------
// LayerNorm LN1: warp-per-token, gather read, HALF output.
// ---------------------------------------------------------------------------
__global__ __launch_bounds__(256) void ln_kernel_h(
    const float* __restrict__ x, const float* __restrict__ g,
    const float* __restrict__ bb, __half* __restrict__ out)
{
    int warp = threadIdx.x >> 5, lane = threadIdx.x & 31;
    int r = blockIdx.x * 8 + warp;
    int b  = r >> 12;
    int wi = (r >> 9) & 7, wj = (r >> 6) & 7;
    int pi = (r >> 3) & 7, pj = r & 7;
    int h = (wi * 8 + pi + 4) & 63;
    int w = (wj * 8 + pj + 4) & 63;
    long src = (long)b * 4096 + h * 64 + w;

    const float4* xp = (const float4*)(x + src * C_DIM);
    float4 v0 = xp[lane * 2], v1 = xp[lane * 2 + 1];
    float s  = v0.x + v0.y + v0.z + v0.w + v1.x + v1.y + v1.z + v1.w;
    float s2 = v0.x*v0.x + v0.y*v0.y + v0.z*v0.z + v0.w*v0.w
             + v1.x*v1.x + v1.y*v1.y + v1.z*v1.z + v1.w*v1.w;
    #pragma unroll
    for (int o = 16; o > 0; o >>= 1) {
        s  += __shfl_xor_sync(0xffffffffu, s, o);
        s2 += __shfl_xor_sync(0xffffffffu, s2, o);
    }
    float mean = s * (1.f / 256.f);
    float var  = s2 * (1.f / 256.f) - mean * mean;
    float rstd = rsqrtf(var + 1e-5f);
    const float4* gp = (const float4*)(g  + lane * 8);
    const float4* bp = (const float4*)(bb + lane * 8);
    float4 g0 = gp[0], g1 = gp[1], b0 = bp[0], b1 = bp[1];
    __half2* op = (__half2*)(out + (long)r * C_DIM + lane * 8);
    op[0] = __floats2half2_rn((v0.x - mean) * rstd * g0.x + b0.x,
                              (v0.y - mean) * rstd * g0.y + b0.y);
    op[1] = __floats2half2_rn((v0.z - mean) * rstd * g0.z + b0.z,
                              (v0.w - mean) * rstd * g0.w + b0.w);
    op[2] = __floats2half2_rn((v1.x - mean) * rstd * g1.x + b1.x,
                              (v1.y - mean) * rstd * g1.y + b1.y);
    op[3] = __floats2half2_rn((v1.z - mean) * rstd * g1.z + b1.z,
                              (v1.w - mean) * rstd * g1.w + b1.w);
}

// ===========================================================================
// FP16 GEMMs: C = epi(A[MxK] @ BT[NxK]^T + bias). A, BT half; acc fp32.
// Fragment strides HASTR=40 halves (conflict-free: bank = gid*20+tig).
// ===========================================================================
#define NSTG 3
#define BM   128
#define BK   32
#define HASTR 40
#define H_A_STAGE (BM * HASTR)                 // 5120 halves

// ---- small tile 128x128, 2 CTAs/SM. EPI 0: fp32 out. 1: GELU + half out. ----
#define SBN 128
#define H_BS_STAGE (SBN * HASTR)
#define HSMEM_S ((NSTG * (H_A_STAGE + H_BS_STAGE)) * 2)    // 61440 B

template<int EPI>
__global__ __launch_bounds__(256, 2) void f16gemm_s(
    const __half* __restrict__ A, const __half* __restrict__ BT,
    const float* __restrict__ bias, const float* __restrict__ R,
    float* __restrict__ Cf, __half* __restrict__ Ch, int M, int N, int K)
{
    extern __shared__ __half hsm[];
    __half* Asm = hsm;
    __half* Bsm = hsm + NSTG * H_A_STAGE;

    int tid  = threadIdx.x;
    int lane = tid & 31, warp = tid >> 5;
    int wm = warp >> 2, wn = warp & 3;
    int bm = blockIdx.y * BM, bn = blockIdx.x * SBN;
    int gid = lane >> 2, tig = lane & 3;

    float acc[4][4][4];
    #pragma unroll
    for (int mt = 0; mt < 4; mt++)
        #pragma unroll
        for (int nt = 0; nt < 4; nt++)
            #pragma unroll
            for (int i = 0; i < 4; i++) acc[mt][nt][i] = 0.f;

    // A: 128 rows x 64B = 512 chunks (2/thread); B same.
    int aR[2], aO[2];
    #pragma unroll
    for (int i = 0; i < 2; i++) {
        int ch = tid + i * 256;
        aR[i] = ch >> 2;  aO[i] = (ch & 3) * 8;   // halves
    }

    int KT = K >> 5;

    #pragma unroll
    for (int s = 0; s < NSTG - 1; s++) {
        int kb = s << 5;
        __half* as = Asm + s * H_A_STAGE;
        __half* bs = Bsm + s * H_BS_STAGE;
        #pragma unroll
        for (int i = 0; i < 2; i++) {
            cp_async16(&as[aR[i] * HASTR + aO[i]], A + (long)(bm + aR[i]) * K + kb + aO[i]);
            cp_async16(&bs[aR[i] * HASTR + aO[i]], BT + (long)(bn + aR[i]) * K + kb + aO[i]);
        }
        cp_commit();
    }

    for (int kt = 0; kt < KT; kt++) {
        if (kt + NSTG - 1 < KT) cp_wait<NSTG - 2>(); else cp_wait<0>();
        __syncthreads();
        int stg = kt % NSTG;
        const __half* as = Asm + stg * H_A_STAGE;
        const __half* bs = Bsm + stg * H_BS_STAGE;
        #pragma unroll
        for (int ks = 0; ks < 2; ks++) {
            uint32_t af[4][4], bf[4][2];
            #pragma unroll
            for (int mt = 0; mt < 4; mt++) {
                int r0 = wm * 64 + mt * 16 + gid;
                int c0 = ks * 16 + 2 * tig;
                af[mt][0] = *(const uint32_t*)&as[r0 * HASTR + c0];
                af[mt][1] = *(const uint32_t*)&as[(r0 + 8) * HASTR + c0];
                af[mt][2] = *(const uint32_t*)&as[r0 * HASTR + c0 + 8];
                af[mt][3] = *(const uint32_t*)&as[(r0 + 8) * HASTR + c0 + 8];
            }
            #pragma unroll
            for (int nt = 0; nt < 4; nt++) {
                int nr = wn * 32 + nt * 8 + gid;
                int c0 = ks * 16 + 2 * tig;
                bf[nt][0] = *(const uint32_t*)&bs[nr * HASTR + c0];
                bf[nt][1] = *(const uint32_t*)&bs[nr * HASTR + c0 + 8];
            }
            #pragma unroll
            for (int mt = 0; mt < 4; mt++)
                #pragma unroll
                for (int nt = 0; nt < 4; nt++)
                    mma_f16(acc[mt][nt], af[mt], bf[nt]);
        }
        if (kt + NSTG - 1 < KT) {
            int kn = kt + NSTG - 1;
            int kb = kn << 5;
            int ds = kn % NSTG;
            __half* asn = Asm + ds * H_A_STAGE;
            __half* bsn = Bsm + ds * H_BS_STAGE;
            #pragma unroll
            for (int i = 0; i < 2; i++) {
                cp_async16(&asn[aR[i] * HASTR + aO[i]], A + (long)(bm + aR[i]) * K + kb + aO[i]);
                cp_async16(&bsn[aR[i] * HASTR + aO[i]], BT + (long)(bn + aR[i]) * K + kb + aO[i]);
            }
            cp_commit();
        }
    }

    #pragma unroll
    for (int mt = 0; mt < 4; mt++) {
        #pragma unroll
        for (int half = 0; half < 2; half++) {
            int row = bm + wm * 64 + mt * 16 + half * 8 + gid;
            #pragma unroll
            for (int nt = 0; nt < 4; nt++) {
                int col = bn + wn * 32 + nt * 8 + 2 * tig;
                float v0 = acc[mt][nt][half * 2 + 0] + bias[col];
                float v1 = acc[mt][nt][half * 2 + 1] + bias[col + 1];
                if (EPI == 1) {
                    v0 = 0.5f * v0 * (1.f + erff(v0 * 0.70710678118654752f));
                    v1 = 0.5f * v1 * (1.f + erff(v1 * 0.70710678118654752f));
                    *(__half2*)(Ch + (long)row * N + col) = __floats2half2_rn(v0, v1);
                } else {
                    float2 o; o.x = v0; o.y = v1;
                    *(float2*)(Cf + (long)row * N + col) = o;
                }
            }
        }
    }
}

// ---- fc2 tile 128x128 with residual, fp32 out (EPI3 specialization kept
//      in the same kernel via R != nullptr is avoided: use template above?)
// fc2 uses EPI 0 path + residual: add a dedicated kernel.
__global__ __launch_bounds__(256, 2) void f16gemm_res(
    const __half* __restrict__ A, const __half* __restrict__ BT,
    const float* __restrict__ bias, const float* __restrict__ R,
    float* __restrict__ Cf, int M, int N, int K)
{
    extern __shared__ __half hsm[];
    __half* Asm = hsm;
    __half* Bsm = hsm + NSTG * H_A_STAGE;

    int tid  = threadIdx.x;
    int lane = tid & 31, warp = tid >> 5;
    int wm = warp >> 2, wn = warp & 3;
    int bm = blockIdx.y * BM, bn = blockIdx.x * SBN;
    int gid = lane >> 2, tig = lane & 3;

    float acc[4][4][4];
    #pragma unroll
    for (int mt = 0; mt < 4; mt++)
        #pragma unroll
        for (int nt = 0; nt < 4; nt++)
            #pragma unroll
            for (int i = 0; i < 4; i++) acc[mt][nt][i] = 0.f;

    int aR[2], aO[2];
    #pragma unroll
    for (int i = 0; i < 2; i++) {
        int ch = tid + i * 256;
        aR[i] = ch >> 2;  aO[i] = (ch & 3) * 8;
    }

    int KT = K >> 5;

    #pragma unroll
    for (int s = 0; s < NSTG - 1; s++) {
        int kb = s << 5;
        __half* as = Asm + s * H_A_STAGE;
        __half* bs = Bsm + s * H_BS_STAGE;
        #pragma unroll
        for (int i = 0; i < 2; i++) {
            cp_async16(&as[aR[i] * HASTR + aO[i]], A + (long)(bm + aR[i]) * K + kb + aO[i]);
            cp_async16(&bs[aR[i] * HASTR + aO[i]], BT + (long)(bn + aR[i]) * K + kb + aO[i]);
        }
        cp_commit();
    }

    for (int kt = 0; kt < KT; kt++) {
        if (kt + NSTG - 1 < KT) cp_wait<NSTG - 2>(); else cp_wait<0>();
        __syncthreads();
        int stg = kt % NSTG;
        const __half* as = Asm + stg * H_A_STAGE;
        const __half* bs = Bsm + stg * H_BS_STAGE;
        #pragma unroll
        for (int ks = 0; ks < 2; ks++) {
            uint32_t af[4][4], bf[4][2];
            #pragma unroll
            for (int mt = 0; mt < 4; mt++) {
                int r0 = wm * 64 + mt * 16 + gid;
                int c0 = ks * 16 + 2 * tig;
                af[mt][0] = *(const uint32_t*)&as[r0 * HASTR + c0];
                af[mt][1] = *(const uint32_t*)&as[(r0 + 8) * HASTR + c0];
                af[mt][2] = *(const uint32_t*)&as[r0 * HASTR + c0 + 8];
                af[mt][3] = *(const uint32_t*)&as[(r0 + 8) * HASTR + c0 + 8];
            }
            #pragma unroll
            for (int nt = 0; nt < 4; nt++) {
                int nr = wn * 32 + nt * 8 + gid;
                int c0 = ks * 16 + 2 * tig;
                bf[nt][0] = *(const uint32_t*)&bs[nr * HASTR + c0];
                bf[nt][1] = *(const uint32_t*)&bs[nr * HASTR + c0 + 8];
            }
            #pragma unroll
            for (int mt = 0; mt < 4; mt++)
                #pragma unroll
                for (int nt = 0; nt < 4; nt++)
                    mma_f16(acc[mt][nt], af[mt], bf[nt]);
        }
        if (kt + NSTG - 1 < KT) {
            int kn = kt + NSTG - 1;
            int kb = kn << 5;
            int ds = kn % NSTG;
            __half* asn = Asm + ds * H_A_STAGE;
            __half* bsn = Bsm + ds * H_BS_STAGE;
            #pragma unroll
            for (int i = 0; i < 2; i++) {
                cp_async16(&asn[aR[i] * HASTR + aO[i]], A + (long)(bm + aR[i]) * K + kb + aO[i]);
                cp_async16(&bsn[aR[i] * HASTR + aO[i]], BT + (long)(bn + aR[i]) * K + kb + aO[i]);
            }
            cp_commit();
        }
    }

    #pragma unroll
    for (int mt = 0; mt < 4; mt++) {
        #pragma unroll
        for (int half = 0; half < 2; half++) {
            int row = bm + wm * 64 + mt * 16 + half * 8 + gid;
            #pragma unroll
            for (int nt = 0; nt < 4; nt++) {
                int col = bn + wn * 32 + nt * 8 + 2 * tig;
                float2 rr = *(const float2*)(R + (long)row * N + col);
                float2 o;
                o.x = acc[mt][nt][half * 2 + 0] + bias[col]     + rr.x;
                o.y = acc[mt][nt][half * 2 + 1] + bias[col + 1] + rr.y;
                *(float2*)(Cf + (long)row * N + col) = o;
            }
        }
    }
}

// ---- big tile 128x256 (1 CTA/SM): wo + scatter + residual -> hs (fp32),
//      fused LN2 -> Y (half). ----
#define TBN2 256
#define H_BB_STAGE (TBN2 * HASTR)
#define HSMEM_B ((NSTG * (H_A_STAGE + H_BB_STAGE)) * 2)    // 92160 B

__global__ __launch_bounds__(256, 1) void f16gemm_ln2(
    const __half* __restrict__ A, const __half* __restrict__ BT,
    const float* __restrict__ bias, const float* __restrict__ R,
    float* __restrict__ C, int M, int N, int K,
    const float* __restrict__ G2, const float* __restrict__ B2,
    __half* __restrict__ Y)
{
    extern __shared__ __half hsm[];
    __half* Asm = hsm;
    __half* Bsm = hsm + NSTG * H_A_STAGE;
    float* red = (float*)hsm;     // reused after mainloop (4KB)

    int tid  = threadIdx.x;
    int lane = tid & 31, warp = tid >> 5;
    int wm = warp >> 2, wn = warp & 3;
    int bm = blockIdx.y * BM, bn = blockIdx.x * TBN2;
    int gid = lane >> 2, tig = lane & 3;

    float acc[4][8][4];
    #pragma unroll
    for (int mt = 0; mt < 4; mt++)
        #pragma unroll
        for (int nt = 0; nt < 8; nt++)
            #pragma unroll
            for (int i = 0; i < 4; i++) acc[mt][nt][i] = 0.f;

    // A: 512 chunks (2/thread); B: 256 rows x 64B = 1024 chunks (4/thread)
    int aR[2], aO[2], bR[4], bO[4];
    #pragma unroll
    for (int i = 0; i < 2; i++) {
        int ch = tid + i * 256;
        aR[i] = ch >> 2;  aO[i] = (ch & 3) * 8;
    }
    #pragma unroll
    for (int i = 0; i < 4; i++) {
        int ch = tid + i * 256;
        bR[i] = ch >> 2;  bO[i] = (ch & 3) * 8;
    }

    int KT = K >> 5;

    #pragma unroll
    for (int s = 0; s < NSTG - 1; s++) {
        int kb = s << 5;
        __half* as = Asm + s * H_A_STAGE;
        __half* bs = Bsm + s * H_BB_STAGE;
        #pragma unroll
        for (int i = 0; i < 2; i++)
            cp_async16(&as[aR[i] * HASTR + aO[i]], A + (long)(bm + aR[i]) * K + kb + aO[i]);
        #pragma unroll
        for (int i = 0; i < 4; i++)
            cp_async16(&bs[bR[i] * HASTR + bO[i]], BT + (long)(bn + bR[i]) * K + kb + bO[i]);
        cp_commit();
    }

    for (int kt = 0; kt < KT; kt++) {
        if (kt + NSTG - 1 < KT) cp_wait<NSTG - 2>(); else cp_wait<0>();
        __syncthreads();
        int stg = kt % NSTG;
        const __half* as = Asm + stg * H_A_STAGE;
        const __half* bs = Bsm + stg * H_BB_STAGE;
        #pragma unroll
        for (int ks = 0; ks < 2; ks++) {
            uint32_t af[4][4], bf[8][2];
            #pragma unroll
            for (int mt = 0; mt < 4; mt++) {
                int r0 = wm * 64 + mt * 16 + gid;
                int c0 = ks * 16 + 2 * tig;
                af[mt][0] = *(const uint32_t*)&as[r0 * HASTR + c0];
                af[mt][1] = *(const uint32_t*)&as[(r0 + 8) * HASTR + c0];
                af[mt][2] = *(const uint32_t*)&as[r0 * HASTR + c0 + 8];
                af[mt][3] = *(const uint32_t*)&as[(r0 + 8) * HASTR + c0 + 8];
            }
            #pragma unroll
            for (int nt = 0; nt < 8; nt++) {
                int nr = wn * 64 + nt * 8 + gid;
                int c0 = ks * 16 + 2 * tig;
                bf[nt][0] = *(const uint32_t*)&bs[nr * HASTR + c0];
                bf[nt][1] = *(const uint32_t*)&bs[nr * HASTR + c0 + 8];
            }
            #pragma unroll
            for (int mt = 0; mt < 4; mt++)
                #pragma unroll
                for (int nt = 0; nt < 8; nt++)
                    mma_f16(acc[mt][nt], af[mt], bf[nt]);
        }
        if (kt + NSTG - 1 < KT) {
            int kn = kt + NSTG - 1;
            int kb = kn << 5;
            int ds = kn % NSTG;
            __half* asn = Asm + ds * H_A_STAGE;
            __half* bsn = Bsm + ds * H_BB_STAGE;
            #pragma unroll
            for (int i = 0; i < 2; i++)
                cp_async16(&asn[aR[i] * HASTR + aO[i]], A + (long)(bm + aR[i]) * K + kb + aO[i]);
            #pragma unroll
            for (int i = 0; i < 4; i++)
                cp_async16(&bsn[bR[i] * HASTR + bO[i]], BT + (long)(bn + bR[i]) * K + kb + bO[i]);
            cp_commit();
        }
    }

    // fused epilogue: hs = acc + bias + residual (scattered), y = LN(hs)
    __syncthreads();
    long orows[4][2];
    float rsum[4][2], rsq[4][2];
    #pragma unroll
    for (int mt = 0; mt < 4; mt++) {
        #pragma unroll
        for (int half = 0; half < 2; half++) {
            int row = bm + wm * 64 + mt * 16 + half * 8 + gid;
            int b  = row >> 12;
            int wi = (row >> 9) & 7, wj = (row >> 6) & 7;
            int pi = (row >> 3) & 7, pj = row & 7;
            int h = (wi * 8 + pi + 4) & 63;
            int w = (wj * 8 + pj + 4) & 63;
            long orow = (long)b * 4096 + h * 64 + w;
            orows[mt][half] = orow;
            float s = 0.f, q = 0.f;
            #pragma unroll
            for (int nt = 0; nt < 8; nt++) {
                int col = bn + wn * 64 + nt * 8 + 2 * tig;
                float v0 = acc[mt][nt][half * 2 + 0] + bias[col];
                float v1 = acc[mt][nt][half * 2 + 1] + bias[col + 1];
                float2 rr = *(const float2*)(R + orow * N + col);
                v0 += rr.x; v1 += rr.y;
                acc[mt][nt][half * 2 + 0] = v0;
                acc[mt][nt][half * 2 + 1] = v1;
                s += v0 + v1;
                q += v0 * v0 + v1 * v1;
                float2 o; o.x = v0; o.y = v1;
                *(float2*)(C + orow * N + col) = o;
            }
            rsum[mt][half] = s; rsq[mt][half] = q;
        }
    }
    #pragma unroll
    for (int mt = 0; mt < 4; mt++) {
        #pragma unroll
        for (int half = 0; half < 2; half++) {
            float s = rsum[mt][half], q = rsq[mt][half];
            s += __shfl_xor_sync(0xffffffffu, s, 1);
            q += __shfl_xor_sync(0xffffffffu, q, 1);
            s += __shfl_xor_sync(0xffffffffu, s, 2);
            q += __shfl_xor_sync(0xffffffffu, q, 2);
            if (tig == 0) {
                int lr = wm * 64 + mt * 16 + half * 8 + gid;
                red[lr * 8 + wn * 2]     = s;
                red[lr * 8 + wn * 2 + 1] = q;
            }
        }
    }
    __syncthreads();
    #pragma unroll
    for (int mt = 0; mt < 4; mt++) {
        #pragma unroll
        for (int half = 0; half < 2; half++) {
            int lr = wm * 64 + mt * 16 + half * 8 + gid;
            float s = red[lr*8+0] + red[lr*8+2] + red[lr*8+4] + red[lr*8+6];
            float q = red[lr*8+1] + red[lr*8+3] + red[lr*8+5] + red[lr*8+7];
            float mean = s * (1.f / 256.f);
            float var  = q * (1.f / 256.f) - mean * mean;
            float rstd = rsqrtf(var + 1e-5f);
            long orow = orows[mt][half];
            #pragma unroll
            for (int nt = 0; nt < 8; nt++) {
                int col = bn + wn * 64 + nt * 8 + 2 * tig;
                float v0 = acc[mt][nt][half * 2 + 0];
                float v1 = acc[mt][nt][half * 2 + 1];
                *(__half2*)(Y + orow * N + col) = __floats2half2_rn(
                    (v0 - mean) * rstd * G2[col]     + B2[col],
                    (v1 - mean) * rstd * G2[col + 1] + B2[col + 1]);
            }
        }
    }
}

// ---------------------------------------------------------------------------
// Tensor-core windowed attention, 1xTF32 (R16 version; output -> HALF).
// ---------------------------------------------------------------------------
#define QSTR 36
#define VSTR 40
#define PSTR 68

__device__ __forceinline__ int bandf(int z) { return z < 56 ? 0 : (z < 60 ? 1 : 2); }

__global__ __launch_bounds__(128, 6) void attn_kernel(
    const float* __restrict__ QKV, const float* __restrict__ bt,
    __half* __restrict__ O)
{
    __shared__ float QKs[64 * QSTR * 2];
    __shared__ float Vs[64 * VSTR];
    __shared__ float btS[228];
    float* Qs = QKs;
    float* Ks = QKs + 64 * QSTR;
    float* Ps = QKs;

    int win  = blockIdx.x;
    int head = blockIdx.y;
    int t = threadIdx.x;
    int warp = t >> 5, lane = t & 31;
    int gid = lane >> 2, tig = lane & 3;
    long base = (long)win * 64 * 768 + head * 32;

    for (int i = t; i < 225; i += 128) btS[i] = bt[i * 8 + head];

    const float scale = 0.17677669529663687f;
    #pragma unroll
    for (int i = 0; i < 4; i++) {
        int idx = t + i * 128;
        int row = idx >> 3, c4 = (idx & 7) * 4;
        const float* src = QKV + base + (long)row * 768 + c4;
        float4 q = *(const float4*)(src);
        q.x *= scale; q.y *= scale; q.z *= scale; q.w *= scale;
        *(float4*)&Qs[row * QSTR + c4] = q;
        *(float4*)&Ks[row * QSTR + c4] = *(const float4*)(src + 256);
        *(float4*)&Vs[row * VSTR + c4] = *(const float4*)(src + 512);
    }
    __syncthreads();

    float sc[4][2][4];
    #pragma unroll
    for (int mt = 0; mt < 4; mt++)
        #pragma unroll
        for (int nt = 0; nt < 2; nt++)
            #pragma unroll
            for (int i = 0; i < 4; i++) sc[mt][nt][i] = 0.f;

    #pragma unroll
    for (int kt = 0; kt < 4; kt++) {
        uint32_t af[4][4], bf[2][2];
        #pragma unroll
        for (int mt = 0; mt < 4; mt++) {
            int r0 = mt * 16 + gid;
            int c0 = kt * 8 + tig;
            af[mt][0] = __float_as_uint(Qs[r0 * QSTR + c0]);
            af[mt][1] = __float_as_uint(Qs[(r0 + 8) * QSTR + c0]);
            af[mt][2] = __float_as_uint(Qs[r0 * QSTR + c0 + 4]);
            af[mt][3] = __float_as_uint(Qs[(r0 + 8) * QSTR + c0 + 4]);
        }
        #pragma unroll
        for (int nt = 0; nt < 2; nt++) {
            int kr = warp * 16 + nt * 8 + gid;
            int kc = kt * 8 + tig;
            bf[nt][0] = __float_as_uint(Ks[kr * QSTR + kc]);
            bf[nt][1] = __float_as_uint(Ks[kr * QSTR + kc + 4]);
        }
        #pragma unroll
        for (int mt = 0; mt < 4; mt++)
            #pragma unroll
            for (int nt = 0; nt < 2; nt++)
                mma_tf32(sc[mt][nt], af[mt], bf[nt]);
    }
    __syncthreads();

    int w_in_b = win & 63;
    int wwi = w_in_b >> 3, wwj = w_in_b & 7;
    bool edge = (wwi == 7) || (wwj == 7);
    #pragma unroll
    for (int mt = 0; mt < 4; mt++) {
        #pragma unroll
        for (int half = 0; half < 2; half++) {
            int r = mt * 16 + half * 8 + gid;
            int yi = r >> 3, xi = r & 7;
            int id_i = edge ? bandf(wwi * 8 + yi) * 3 + bandf(wwj * 8 + xi) : 0;
            #pragma unroll
            for (int nt = 0; nt < 2; nt++) {
                int c0 = warp * 16 + nt * 8 + 2 * tig;
                float v0 = sc[mt][nt][half * 2 + 0];
                float v1 = sc[mt][nt][half * 2 + 1];
                #pragma unroll
                for (int j = 0; j < 2; j++) {
                    int c = c0 + j;
                    int yj = c >> 3, xj = c & 7;
                    float add = btS[(yi - yj + 7) * 15 + (xi - xj + 7)];
                    if (edge) {
                        int id_j = bandf(wwi * 8 + yj) * 3 + bandf(wwj * 8 + xj);
                        if (id_i != id_j) add -= 100.f;
                    }
                    if (j == 0) v0 += add; else v1 += add;
                }
                float2 st; st.x = v0; st.y = v1;
                *(float2*)&Ps[r * PSTR + c0] = st;
            }
        }
    }
    __syncthreads();

    {
        int row = t >> 1;
        int c0 = (t & 1) * 32;
        float4 e[8];
        float mx = -1e30f;
        #pragma unroll
        for (int i = 0; i < 8; i++) {
            e[i] = *(const float4*)&Ps[row * PSTR + c0 + i * 4];
            mx = fmaxf(mx, fmaxf(fmaxf(e[i].x, e[i].y), fmaxf(e[i].z, e[i].w)));
        }
        mx = fmaxf(mx, __shfl_xor_sync(0xffffffffu, mx, 1));
        float sum = 0.f;
        #pragma unroll
        for (int i = 0; i < 8; i++) {
            e[i].x = __expf(e[i].x - mx); e[i].y = __expf(e[i].y - mx);
            e[i].z = __expf(e[i].z - mx); e[i].w = __expf(e[i].w - mx);
            sum += e[i].x + e[i].y + e[i].z + e[i].w;
        }
        sum += __shfl_xor_sync(0xffffffffu, sum, 1);
        float rs = 1.f / sum;
        #pragma unroll
        for (int i = 0; i < 8; i++) {
            e[i].x *= rs; e[i].y *= rs; e[i].z *= rs; e[i].w *= rs;
            *(float4*)&Ps[row * PSTR + c0 + i * 4] = e[i];
        }
    }
    __syncthreads();

    float oc[4][4];
    #pragma unroll
    for (int nt = 0; nt < 4; nt++)
        #pragma unroll
        for (int i = 0; i < 4; i++) oc[nt][i] = 0.f;

    #pragma unroll
    for (int kt = 0; kt < 8; kt++) {
        uint32_t af[4], bf[4][2];
        int r0 = warp * 16 + gid;
        int c0 = kt * 8 + tig;
        af[0] = __float_as_uint(Ps[r0 * PSTR + c0]);
        af[1] = __float_as_uint(Ps[(r0 + 8) * PSTR + c0]);
        af[2] = __float_as_uint(Ps[r0 * PSTR + c0 + 4]);
        af[3] = __float_as_uint(Ps[(r0 + 8) * PSTR + c0 + 4]);
        #pragma unroll
        for (int nt = 0; nt < 4; nt++) {
            int vr = kt * 8 + tig;
            int vc = nt * 8 + gid;
            bf[nt][0] = __float_as_uint(Vs[vr * VSTR + vc]);
            bf[nt][1] = __float_as_uint(Vs[(vr + 4) * VSTR + vc]);
        }
        #pragma unroll
        for (int nt = 0; nt < 4; nt++)
            mma_tf32(oc[nt], af, bf[nt]);
    }

    long obase = ((long)win * 64) * C_DIM + head * 32;
    #pragma unroll
    for (int half = 0; half < 2; half++) {
        int row = warp * 16 + half * 8 + gid;
        #pragma unroll
        for (int nt = 0; nt < 4; nt++) {
            int col = nt * 8 + 2 * tig;
            *(__half2*)(O + obase + (long)row * C_DIM + col) =
                __floats2half2_rn(oc[nt][half * 2 + 0], oc[nt][half * 2 + 1]);
        }
    }
}

// ---------------------------------------------------------------------------
// Launch
// ---------------------------------------------------------------------------
extern "C" void kernel_launch(void* const* d_in, const int* in_sizes, int n_in,
                              void* d_out, int out_size)
{
    const float* hidden = (const float*)d_in[0];
    const float* ln1_g  = (const float*)d_in[1];
    const float* ln1_b  = (const float*)d_in[2];
    const float* wq     = (const float*)d_in[3];
    const float* bq     = (const float*)d_in[4];
    const float* wk     = (const float*)d_in[5];
    const float* bk     = (const float*)d_in[6];
    const float* wv     = (const float*)d_in[7];
    const float* bv     = (const float*)d_in[8];
    const float* bt     = (const float*)d_in[9];
    const float* wo     = (const float*)d_in[10];
    const float* bo     = (const float*)d_in[11];
    const float* ln2_g  = (const float*)d_in[12];
    const float* ln2_b  = (const float*)d_in[13];
    const float* w1     = (const float*)d_in[14];
    const float* b1     = (const float*)d_in[15];
    const float* w2     = (const float*)d_in[16];
    const float* b2     = (const float*)d_in[17];
    float* out = (float*)d_out;

    __half *p_xw, *p_att, *p_y, *p_mid, *p_wqkvT, *p_w1T, *p_w2T, *p_woT;
    float  *p_qkv, *p_hs, *p_bqkv;
    cudaGetSymbolAddress((void**)&p_xw,    g_xw_h);
    cudaGetSymbolAddress((void**)&p_qkv,   g_qkv);
    cudaGetSymbolAddress((void**)&p_att,   g_att_h);
    cudaGetSymbolAddress((void**)&p_hs,    g_hs);
    cudaGetSymbolAddress((void**)&p_y,     g_y_h);
    cudaGetSymbolAddress((void**)&p_mid,   g_mid_h);
    cudaGetSymbolAddress((void**)&p_wqkvT, g_wqkvT);
    cudaGetSymbolAddress((void**)&p_bqkv,  g_bqkv);
    cudaGetSymbolAddress((void**)&p_w1T,   g_w1T);
    cudaGetSymbolAddress((void**)&p_w2T,   g_w2T);
    cudaGetSymbolAddress((void**)&p_woT,   g_woT);

    cudaFuncSetAttribute(f16gemm_s<0>, cudaFuncAttributeMaxDynamicSharedMemorySize, HSMEM_S);
    cudaFuncSetAttribute(f16gemm_s<1>, cudaFuncAttributeMaxDynamicSharedMemorySize, HSMEM_S);
    cudaFuncSetAttribute(f16gemm_res, cudaFuncAttributeMaxDynamicSharedMemorySize, HSMEM_S);
    cudaFuncSetAttribute(f16gemm_ln2, cudaFuncAttributeMaxDynamicSharedMemorySize, HSMEM_B);

    dim3 blk(256);

    pack_qkvT<<<768, blk>>>(wq, wk, wv, bq, bk, bv, p_wqkvT, p_bqkv);
    transpose_w1<<<1024, blk>>>(w1, p_w1T);
    transpose_w2<<<1024, blk>>>(w2, p_w2T);
    transpose_wo<<<256, blk>>>(wo, p_woT);
    ln_kernel_h<<<M_TOK / 8, blk>>>(hidden, ln1_g, ln1_b, p_xw);

    // QKV projection (fp16 mma) -> fp32 qkv
    f16gemm_s<0><<<dim3(768 / SBN, M_TOK / BM), blk, HSMEM_S>>>(
        p_xw, p_wqkvT, p_bqkv, nullptr, p_qkv, nullptr, M_TOK, 768, C_DIM);
    attn_kernel<<<dim3(2048, 8), dim3(128)>>>(p_qkv, bt, p_att);
    // wo + scatter + residual -> hs (fp32), fused LN2 -> y (half)
    f16gemm_ln2<<<dim3(C_DIM / TBN2, M_TOK / BM), blk, HSMEM_B>>>(
        p_att, p_woT, bo, hidden, p_hs, M_TOK, C_DIM, C_DIM,
        ln2_g, ln2_b, p_y);
    // fc1 + GELU -> half mid
    f16gemm_s<1><<<dim3(DFF / SBN, M_TOK / BM), blk, HSMEM_S>>>(
        p_y, p_w1T, b1, nullptr, nullptr, p_mid, M_TOK, DFF, C_DIM);
    // fc2 + residual -> out (fp32)
    f16gemm_res<<<dim3(C_DIM / SBN, M_TOK / BM), blk, HSMEM_S>>>(
        p_mid, p_w2T, b2, p_hs, out, M_TOK, C_DIM, DFF);
}